// round 2
// baseline (speedup 1.0000x reference)
#include <cuda_runtime.h>
#include <cuda_bf16.h>

// ---------------------------------------------------------------------------
// Scratch (allocation-free: __device__ globals)
// ---------------------------------------------------------------------------
__device__ float g_bufA[26 * 1024 * 1024];   // 104 MB ping
__device__ float g_bufB[26 * 1024 * 1024];   // 104 MB pong
__device__ float g_wq[52000];                // quantized weights arena
__device__ float g_gap[2048];                // [8,256] pooled features

// wq arena offsets
#define WQ_CONV1 0
#define WQ_B1DW  1728
#define WQ_B1PW  2304
#define WQ_B2DW  6400
#define WQ_B2PW  6976
#define WQ_B3DW  15168
#define WQ_B3PW  16320
#define WQ_FC    49088

__device__ __forceinline__ float fqv(float x, float s, float lo, float hi) {
    float q = rintf(x / s);
    q = fminf(fmaxf(q, lo), hi);
    return q * s;
}

// ---------------------------------------------------------------------------
// Weight fake-quant: per-tensor scale = max|w|/127, q = clip(rint(w/s),-127,127)*s
// One block per tensor.
// ---------------------------------------------------------------------------
__global__ void wq_kernel(const float* w0, const float* w1, const float* w2,
                          const float* w3, const float* w4, const float* w5,
                          const float* w6, const float* w7) {
    __shared__ float red[256];
    const float* srcs[8] = {w0, w1, w2, w3, w4, w5, w6, w7};
    const int sizes[8] = {1728, 576, 4096, 576, 8192, 1152, 32768, 2560};
    const int offs[8]  = {WQ_CONV1, WQ_B1DW, WQ_B1PW, WQ_B2DW,
                          WQ_B2PW, WQ_B3DW, WQ_B3PW, WQ_FC};
    int t = blockIdx.x;
    const float* w = srcs[t];
    int n = sizes[t];
    float* dst = g_wq + offs[t];

    float m = 0.0f;
    for (int i = threadIdx.x; i < n; i += 256) m = fmaxf(m, fabsf(w[i]));
    red[threadIdx.x] = m;
    __syncthreads();
    for (int s = 128; s > 0; s >>= 1) {
        if (threadIdx.x < s)
            red[threadIdx.x] = fmaxf(red[threadIdx.x], red[threadIdx.x + s]);
        __syncthreads();
    }
    float scale = red[0] / 127.0f;
    for (int i = threadIdx.x; i < n; i += 256) {
        float q = rintf(w[i] / scale);
        q = fminf(fmaxf(q, -127.0f), 127.0f);
        dst[i] = q * scale;
    }
}

// ---------------------------------------------------------------------------
// conv1: fq(x, s0, int8) -> 3x3 conv (3->64, pad 1) + bias -> relu -> fq(s1, uint8)
// Block: 32x8 spatial tile for one image; loops all 64 output channels.
// ---------------------------------------------------------------------------
__global__ void conv1_kernel(const float* __restrict__ x,
                             const float* __restrict__ bias,
                             const float* __restrict__ scales,
                             float* __restrict__ out) {
    __shared__ float s_in[3][10][34];
    __shared__ float s_w[1728];
    int n = blockIdx.z;
    int x0 = blockIdx.x * 32, y0 = blockIdx.y * 8;
    int tid = threadIdx.y * 32 + threadIdx.x;
    float s0 = scales[0], s1 = scales[1];

    for (int i = tid; i < 1728; i += 256) s_w[i] = g_wq[WQ_CONV1 + i];

    for (int i = tid; i < 3 * 10 * 34; i += 256) {
        int c = i / 340;
        int r = i % 340;
        int ly = r / 34, lx = r % 34;
        int gy = y0 + ly - 1, gx = x0 + lx - 1;
        float v = 0.0f;
        if (gy >= 0 && gy < 224 && gx >= 0 && gx < 224)
            v = fqv(x[((n * 3 + c) * 224 + gy) * 224 + gx], s0, -128.0f, 127.0f);
        s_in[c][ly][lx] = v;
    }
    __syncthreads();

    int tx = threadIdx.x, ty = threadIdx.y;
    for (int oc = 0; oc < 64; oc++) {
        float acc = bias[oc];
        #pragma unroll
        for (int c = 0; c < 3; c++)
            #pragma unroll
            for (int ky = 0; ky < 3; ky++)
                #pragma unroll
                for (int kx = 0; kx < 3; kx++)
                    acc += s_in[c][ty + ky][tx + kx] * s_w[oc * 27 + c * 9 + ky * 3 + kx];
        acc = fmaxf(acc, 0.0f);
        acc = fqv(acc, s1, 0.0f, 255.0f);
        out[((n * 64 + oc) * 224 + (y0 + ty)) * 224 + (x0 + tx)] = acc;
    }
}

// ---------------------------------------------------------------------------
// Depthwise 3x3 (pad 1) + bias + relu + fq(uint8). 4 outputs / thread along x.
// ---------------------------------------------------------------------------
__global__ void dw_kernel(const float* __restrict__ in, float* __restrict__ out,
                          int woff, const float* __restrict__ bias,
                          int C, int H, int W,
                          const float* __restrict__ scales, int si) {
    int idx = blockIdx.x * 256 + threadIdx.x;
    int W4 = W >> 2;
    int x4 = (idx % W4) * 4;
    int t = idx / W4;
    int yy = t % H; t /= H;
    int c = t % C;
    int n = t / C;

    const float* wp = g_wq + woff + c * 9;
    float w[9];
    #pragma unroll
    for (int i = 0; i < 9; i++) w[i] = wp[i];

    const float* ip = in + (size_t)(n * C + c) * H * W;
    float v[3][6];
    #pragma unroll
    for (int ky = 0; ky < 3; ky++) {
        int gy = yy + ky - 1;
        bool rowok = (gy >= 0) && (gy < H);
        const float* rp = ip + (size_t)gy * W;
        #pragma unroll
        for (int dx = 0; dx < 6; dx++) {
            int gx = x4 + dx - 1;
            v[ky][dx] = (rowok && gx >= 0 && gx < W) ? rp[gx] : 0.0f;
        }
    }

    float b = bias[c], s = scales[si];
    float4 r;
    float* rr = &r.x;
    #pragma unroll
    for (int j = 0; j < 4; j++) {
        float acc = b;
        #pragma unroll
        for (int ky = 0; ky < 3; ky++)
            #pragma unroll
            for (int kx = 0; kx < 3; kx++)
                acc += v[ky][j + kx] * w[ky * 3 + kx];
        rr[j] = fqv(fmaxf(acc, 0.0f), s, 0.0f, 255.0f);
    }
    *(float4*)&out[(size_t)idx * 4] = r;
}

// ---------------------------------------------------------------------------
// Pointwise 1x1 (CIN->COUT) + bias + relu + fq(uint8).
// Block tile: 64 pixels x 64 oc; thread tile 4x4 (256 threads).
// Dynamic smem: s_x [CIN][64] + s_w [CIN][64].
// ---------------------------------------------------------------------------
template <int CIN, int COUT>
__global__ void pw_kernel(const float* __restrict__ in, float* __restrict__ out,
                          int woff, const float* __restrict__ bias,
                          int HW, const float* __restrict__ scales, int si) {
    extern __shared__ float smem[];
    float* s_x = smem;             // [CIN][64] pixels
    float* s_w = smem + CIN * 64;  // [CIN][64] current oc chunk
    int tid = threadIdx.x;
    int n = blockIdx.y;
    int hw0 = blockIdx.x * 64;

    for (int e = tid; e < CIN * 64; e += 256) {
        int ic = e >> 6, pix = e & 63;
        s_x[e] = in[(size_t)(n * CIN + ic) * HW + hw0 + pix];
    }

    float sact = scales[si];
    int px = (tid & 15) * 4;    // pixel base
    int ocl = (tid >> 4) * 4;   // oc base within chunk

    for (int oc0 = 0; oc0 < COUT; oc0 += 64) {
        __syncthreads();
        for (int e = tid; e < CIN * 64; e += 256) {
            int ic = e >> 6, o = e & 63;
            s_w[e] = g_wq[woff + (oc0 + o) * CIN + ic];
        }
        __syncthreads();

        float acc[4][4];
        #pragma unroll
        for (int o = 0; o < 4; o++)
            #pragma unroll
            for (int p = 0; p < 4; p++) acc[o][p] = 0.0f;

        #pragma unroll 4
        for (int ic = 0; ic < CIN; ic++) {
            float4 xv = *(const float4*)&s_x[ic * 64 + px];
            float4 wv = *(const float4*)&s_w[ic * 64 + ocl];
            acc[0][0] += wv.x * xv.x; acc[0][1] += wv.x * xv.y;
            acc[0][2] += wv.x * xv.z; acc[0][3] += wv.x * xv.w;
            acc[1][0] += wv.y * xv.x; acc[1][1] += wv.y * xv.y;
            acc[1][2] += wv.y * xv.z; acc[1][3] += wv.y * xv.w;
            acc[2][0] += wv.z * xv.x; acc[2][1] += wv.z * xv.y;
            acc[2][2] += wv.z * xv.z; acc[2][3] += wv.z * xv.w;
            acc[3][0] += wv.w * xv.x; acc[3][1] += wv.w * xv.y;
            acc[3][2] += wv.w * xv.z; acc[3][3] += wv.w * xv.w;
        }

        #pragma unroll
        for (int o = 0; o < 4; o++) {
            int oc = oc0 + ocl + o;
            float b = bias[oc];
            float4 r;
            r.x = fqv(fmaxf(acc[o][0] + b, 0.0f), sact, 0.0f, 255.0f);
            r.y = fqv(fmaxf(acc[o][1] + b, 0.0f), sact, 0.0f, 255.0f);
            r.z = fqv(fmaxf(acc[o][2] + b, 0.0f), sact, 0.0f, 255.0f);
            r.w = fqv(fmaxf(acc[o][3] + b, 0.0f), sact, 0.0f, 255.0f);
            *(float4*)&out[(size_t)(n * COUT + oc) * HW + hw0 + px] = r;
        }
    }
}

// ---------------------------------------------------------------------------
// 2x2 maxpool stride 2 + fq(int8). 2 outputs / thread, float4 row loads.
// ---------------------------------------------------------------------------
__global__ void pool_kernel(const float* __restrict__ in, float* __restrict__ out,
                            int C, int H, int W,
                            const float* __restrict__ scales, int si) {
    int OH = H >> 1, OW = W >> 1, OW2 = OW >> 1;
    int idx = blockIdx.x * 256 + threadIdx.x;
    int ox = (idx % OW2) * 2;
    int t = idx / OW2;
    int oy = t % OH; t /= OH;
    int c = t % C;
    int n = t / C;
    const float* ip = in + ((size_t)(n * C + c) * H + oy * 2) * W + ox * 2;
    float4 a = *(const float4*)ip;
    float4 b = *(const float4*)(ip + W);
    float s = scales[si];
    float2 r;
    r.x = fqv(fmaxf(fmaxf(a.x, a.y), fmaxf(b.x, b.y)), s, -128.0f, 127.0f);
    r.y = fqv(fmaxf(fmaxf(a.z, a.w), fmaxf(b.z, b.w)), s, -128.0f, 127.0f);
    *(float2*)&out[(size_t)idx * 2] = r;
}

// ---------------------------------------------------------------------------
// Global avg pool over 28x28 + fq(int8) -> g_gap. One block per (n,c).
// ---------------------------------------------------------------------------
__global__ void gap_kernel(const float* __restrict__ in,
                           const float* __restrict__ scales) {
    __shared__ float red[128];
    int bc = blockIdx.x;  // n*256 + c
    const float* ip = in + (size_t)bc * 784;
    float sum = 0.0f;
    for (int i = threadIdx.x; i < 784; i += 128) sum += ip[i];
    red[threadIdx.x] = sum;
    __syncthreads();
    for (int s = 64; s > 0; s >>= 1) {
        if (threadIdx.x < s) red[threadIdx.x] += red[threadIdx.x + s];
        __syncthreads();
    }
    if (threadIdx.x == 0)
        g_gap[bc] = fqv(red[0] * (1.0f / 784.0f), scales[11], -128.0f, 127.0f);
}

// ---------------------------------------------------------------------------
// FC: [8,256] @ Wq^T + b -> [8,10]
// ---------------------------------------------------------------------------
__global__ void fc_kernel(const float* __restrict__ fc_b, float* __restrict__ out) {
    int t = threadIdx.x;
    if (t < 80) {
        int n = t / 10, k = t % 10;
        float acc = fc_b[k];
        const float* w = g_wq + WQ_FC + k * 256;
        const float* g = g_gap + n * 256;
        #pragma unroll 8
        for (int i = 0; i < 256; i++) acc += w[i] * g[i];
        out[t] = acc;
    }
}

// ---------------------------------------------------------------------------
// Launch
// ---------------------------------------------------------------------------
extern "C" void kernel_launch(void* const* d_in, const int* in_sizes, int n_in,
                              void* d_out, int out_size) {
    const float* x       = (const float*)d_in[0];
    const float* scales  = (const float*)d_in[1];
    const float* conv1_w = (const float*)d_in[2];
    const float* conv1_b = (const float*)d_in[3];
    const float* b1_dw_w = (const float*)d_in[4];
    const float* b1_dw_b = (const float*)d_in[5];
    const float* b1_pw_w = (const float*)d_in[6];
    const float* b1_pw_b = (const float*)d_in[7];
    const float* b2_dw_w = (const float*)d_in[8];
    const float* b2_dw_b = (const float*)d_in[9];
    const float* b2_pw_w = (const float*)d_in[10];
    const float* b2_pw_b = (const float*)d_in[11];
    const float* b3_dw_w = (const float*)d_in[12];
    const float* b3_dw_b = (const float*)d_in[13];
    const float* b3_pw_w = (const float*)d_in[14];
    const float* b3_pw_b = (const float*)d_in[15];
    const float* fc_w    = (const float*)d_in[16];
    const float* fc_b    = (const float*)d_in[17];
    float* out = (float*)d_out;

    float *pA = nullptr, *pB = nullptr;
    cudaGetSymbolAddress((void**)&pA, g_bufA);
    cudaGetSymbolAddress((void**)&pB, g_bufB);

    // raise dynamic smem limit for the CIN=128 pointwise (64 KB)
    cudaFuncSetAttribute(pw_kernel<128, 256>,
                         cudaFuncAttributeMaxDynamicSharedMemorySize, 65536);

    // 1) quantize all weights
    wq_kernel<<<8, 256>>>(conv1_w, b1_dw_w, b1_pw_w, b2_dw_w,
                          b2_pw_w, b3_dw_w, b3_pw_w, fc_w);

    // 2) conv1 (+input fq, relu, fq s1) -> A
    {
        dim3 cb(32, 8), cg(7, 28, 8);
        conv1_kernel<<<cg, cb>>>(x, conv1_b, scales, pA);
    }

    // block 1 @ 224x224, C=64
    dw_kernel<<<25088, 256>>>(pA, pB, WQ_B1DW, b1_dw_b, 64, 224, 224, scales, 2);
    pw_kernel<64, 64><<<dim3(784, 8), 256, 32768>>>(pB, pA, WQ_B1PW, b1_pw_b, 50176, scales, 3);
    pool_kernel<<<12544, 256>>>(pA, pB, 64, 224, 224, scales, 4);

    // block 2 @ 112x112, 64 -> 128
    dw_kernel<<<6272, 256>>>(pB, pA, WQ_B2DW, b2_dw_b, 64, 112, 112, scales, 5);
    pw_kernel<64, 128><<<dim3(196, 8), 256, 32768>>>(pA, pB, WQ_B2PW, b2_pw_b, 12544, scales, 6);
    pool_kernel<<<6272, 256>>>(pB, pA, 128, 112, 112, scales, 7);

    // block 3 @ 56x56, 128 -> 256
    dw_kernel<<<3136, 256>>>(pA, pB, WQ_B3DW, b3_dw_b, 128, 56, 56, scales, 8);
    pw_kernel<128, 256><<<dim3(49, 8), 256, 65536>>>(pB, pA, WQ_B3PW, b3_pw_b, 3136, scales, 9);
    pool_kernel<<<3136, 256>>>(pA, pB, 256, 56, 56, scales, 10);

    // head
    gap_kernel<<<2048, 128>>>(pB, scales);
    fc_kernel<<<1, 128>>>(fc_b, out);
}

// round 3
// speedup vs baseline: 1.1889x; 1.1889x over previous
#include <cuda_runtime.h>
#include <cuda_bf16.h>

// ---------------------------------------------------------------------------
// Scratch (allocation-free: __device__ globals)
// ---------------------------------------------------------------------------
__device__ float g_bufA[26 * 1024 * 1024];   // 104 MB ping
__device__ float g_bufB[26 * 1024 * 1024];   // 104 MB pong
__device__ float g_wq[52000];                // quantized weights arena
__device__ float g_gap[2048];                // [8,256] pooled features

// wq arena offsets
#define WQ_CONV1 0
#define WQ_B1DW  1728
#define WQ_B1PW  2304
#define WQ_B2DW  6400
#define WQ_B2PW  6976
#define WQ_B3DW  15168
#define WQ_B3PW  16320
#define WQ_FC    49088

__device__ __forceinline__ float fqv(float x, float s, float lo, float hi) {
    float q = rintf(x / s);
    q = fminf(fmaxf(q, lo), hi);
    return q * s;
}

// ---------------------------------------------------------------------------
// Weight fake-quant. One block per tensor.
// ---------------------------------------------------------------------------
__global__ void wq_kernel(const float* w0, const float* w1, const float* w2,
                          const float* w3, const float* w4, const float* w5,
                          const float* w6, const float* w7) {
    __shared__ float red[256];
    const float* srcs[8] = {w0, w1, w2, w3, w4, w5, w6, w7};
    const int sizes[8] = {1728, 576, 4096, 576, 8192, 1152, 32768, 2560};
    const int offs[8]  = {WQ_CONV1, WQ_B1DW, WQ_B1PW, WQ_B2DW,
                          WQ_B2PW, WQ_B3DW, WQ_B3PW, WQ_FC};
    int t = blockIdx.x;
    const float* w = srcs[t];
    int n = sizes[t];
    float* dst = g_wq + offs[t];

    float m = 0.0f;
    for (int i = threadIdx.x; i < n; i += 256) m = fmaxf(m, fabsf(w[i]));
    red[threadIdx.x] = m;
    __syncthreads();
    for (int s = 128; s > 0; s >>= 1) {
        if (threadIdx.x < s)
            red[threadIdx.x] = fmaxf(red[threadIdx.x], red[threadIdx.x + s]);
        __syncthreads();
    }
    float scale = red[0] / 127.0f;
    for (int i = threadIdx.x; i < n; i += 256) {
        float q = rintf(w[i] / scale);
        q = fminf(fmaxf(q, -127.0f), 127.0f);
        dst[i] = q * scale;
    }
}

// ---------------------------------------------------------------------------
// conv1: fq(x,s0,int8) -> 3x3 conv (3->64, pad 1) + bias -> relu -> fq(s1,u8)
// Block (8,32): 32x32 spatial tile, 4 px per thread, input patch in registers.
// ---------------------------------------------------------------------------
__global__ void conv1_kernel(const float* __restrict__ x,
                             const float* __restrict__ bias,
                             const float* __restrict__ scales,
                             float* __restrict__ out) {
    __shared__ float s_in[3][34][34];
    __shared__ float s_w[1728];
    int n = blockIdx.z;
    int x0 = blockIdx.x * 32, y0 = blockIdx.y * 32;
    int tid = threadIdx.y * 8 + threadIdx.x;
    float s0 = scales[0], s1 = scales[1];

    for (int i = tid; i < 1728; i += 256) s_w[i] = g_wq[WQ_CONV1 + i];

    for (int i = tid; i < 3 * 34 * 34; i += 256) {
        int c = i / 1156;
        int r = i % 1156;
        int ly = r / 34, lx = r % 34;
        int gy = y0 + ly - 1, gx = x0 + lx - 1;
        float v = 0.0f;
        if (gy >= 0 && gy < 224 && gx >= 0 && gx < 224)
            v = fqv(x[((n * 3 + c) * 224 + gy) * 224 + gx], s0, -128.0f, 127.0f);
        s_in[c][ly][lx] = v;
    }
    __syncthreads();

    int tx = threadIdx.x, ty = threadIdx.y;
    int x4 = tx * 4;

    // input patch to registers: 3 ch x 3 rows x 6 cols
    float vin[3][3][6];
    #pragma unroll
    for (int c = 0; c < 3; c++)
        #pragma unroll
        for (int ky = 0; ky < 3; ky++)
            #pragma unroll
            for (int dx = 0; dx < 6; dx++)
                vin[c][ky][dx] = s_in[c][ty + ky][x4 + dx];

    size_t obase = ((size_t)(n * 64) * 224 + (y0 + ty)) * 224 + x0 + x4;
    for (int oc = 0; oc < 64; oc++) {
        float b = bias[oc];
        float acc0 = b, acc1 = b, acc2 = b, acc3 = b;
        const float* wp = &s_w[oc * 27];
        #pragma unroll
        for (int c = 0; c < 3; c++)
            #pragma unroll
            for (int ky = 0; ky < 3; ky++)
                #pragma unroll
                for (int kx = 0; kx < 3; kx++) {
                    float w = wp[c * 9 + ky * 3 + kx];
                    acc0 += vin[c][ky][kx + 0] * w;
                    acc1 += vin[c][ky][kx + 1] * w;
                    acc2 += vin[c][ky][kx + 2] * w;
                    acc3 += vin[c][ky][kx + 3] * w;
                }
        float4 r;
        r.x = fqv(fmaxf(acc0, 0.0f), s1, 0.0f, 255.0f);
        r.y = fqv(fmaxf(acc1, 0.0f), s1, 0.0f, 255.0f);
        r.z = fqv(fmaxf(acc2, 0.0f), s1, 0.0f, 255.0f);
        r.w = fqv(fmaxf(acc3, 0.0f), s1, 0.0f, 255.0f);
        *(float4*)&out[obase + (size_t)oc * 224 * 224] = r;
    }
}

// ---------------------------------------------------------------------------
// Depthwise 3x3 (pad 1) + bias + relu + fq(uint8). 4 outputs / thread along x.
// Aligned float4 row loads + 2 edge scalars (9 LDG vs 18).
// ---------------------------------------------------------------------------
__global__ void dw_kernel(const float* __restrict__ in, float* __restrict__ out,
                          int woff, const float* __restrict__ bias,
                          int C, int H, int W,
                          const float* __restrict__ scales, int si) {
    int idx = blockIdx.x * 256 + threadIdx.x;
    int W4 = W >> 2;
    int x4 = (idx % W4) * 4;
    int t = idx / W4;
    int yy = t % H; t /= H;
    int c = t % C;
    int n = t / C;

    const float* wp = g_wq + woff + c * 9;
    float w[9];
    #pragma unroll
    for (int i = 0; i < 9; i++) w[i] = wp[i];

    const float* ip = in + (size_t)(n * C + c) * H * W;
    float v[3][6];
    #pragma unroll
    for (int ky = 0; ky < 3; ky++) {
        int gy = yy + ky - 1;
        bool rowok = (gy >= 0) && (gy < H);
        const float* rp = ip + (size_t)gy * W;
        float4 m = make_float4(0.f, 0.f, 0.f, 0.f);
        float lft = 0.f, rgt = 0.f;
        if (rowok) {
            m = *(const float4*)&rp[x4];
            if (x4 > 0) lft = rp[x4 - 1];
            if (x4 + 4 < W) rgt = rp[x4 + 4];
        }
        v[ky][0] = lft; v[ky][1] = m.x; v[ky][2] = m.y;
        v[ky][3] = m.z; v[ky][4] = m.w; v[ky][5] = rgt;
    }

    float b = bias[c], s = scales[si];
    float4 r;
    float* rr = &r.x;
    #pragma unroll
    for (int j = 0; j < 4; j++) {
        float acc = b;
        #pragma unroll
        for (int ky = 0; ky < 3; ky++)
            #pragma unroll
            for (int kx = 0; kx < 3; kx++)
                acc += v[ky][j + kx] * w[ky * 3 + kx];
        rr[j] = fqv(fmaxf(acc, 0.0f), s, 0.0f, 255.0f);
    }
    *(float4*)&out[(size_t)idx * 4] = r;
}

// ---------------------------------------------------------------------------
// Pointwise 1x1 (CIN->COUT) + bias + relu + fq(uint8).
// Block tile: 256 pixels x 64 oc; thread tile 8x8 (256 threads).
// Thread pixels split {4p, 128+4p} so LDS.128 is lane-dense.
// Dynamic smem: s_x [CIN][256] + s_w [CIN][64].
// ---------------------------------------------------------------------------
template <int CIN, int COUT>
__global__ void __launch_bounds__(256)
pw_kernel(const float* __restrict__ in, float* __restrict__ out,
          int woff, const float* __restrict__ bias,
          int HW, const float* __restrict__ scales, int si) {
    extern __shared__ float smem[];
    float* s_x = smem;              // [CIN][256]
    float* s_w = smem + CIN * 256;  // [CIN][64] current oc chunk
    int tid = threadIdx.x;
    int n = blockIdx.y;
    int hw0 = blockIdx.x * 256;

    for (int e = tid * 4; e < CIN * 256; e += 1024) {
        int ic = e >> 8, pix = e & 255;
        *(float4*)&s_x[e] =
            *(const float4*)&in[(size_t)(n * CIN + ic) * HW + hw0 + pix];
    }

    float sact = scales[si];
    int pxA = (tid & 31) * 4;       // pixel group A
    int pxB = 128 + pxA;            // pixel group B
    int ocl = (tid >> 5) * 8;       // oc base within 64-oc chunk (warp-uniform)

    for (int oc0 = 0; oc0 < COUT; oc0 += 64) {
        __syncthreads();
        for (int e = tid; e < CIN * 64; e += 256) {
            int ic = e >> 6, o = e & 63;
            s_w[e] = g_wq[woff + (oc0 + o) * CIN + ic];
        }
        __syncthreads();

        float acc[8][8];
        #pragma unroll
        for (int o = 0; o < 8; o++)
            #pragma unroll
            for (int p = 0; p < 8; p++) acc[o][p] = 0.0f;

        #pragma unroll 4
        for (int ic = 0; ic < CIN; ic++) {
            float4 xa = *(const float4*)&s_x[ic * 256 + pxA];
            float4 xb = *(const float4*)&s_x[ic * 256 + pxB];
            float4 w0 = *(const float4*)&s_w[ic * 64 + ocl];
            float4 w1 = *(const float4*)&s_w[ic * 64 + ocl + 4];
            const float wv[8] = {w0.x, w0.y, w0.z, w0.w, w1.x, w1.y, w1.z, w1.w};
            #pragma unroll
            for (int o = 0; o < 8; o++) {
                acc[o][0] += wv[o] * xa.x; acc[o][1] += wv[o] * xa.y;
                acc[o][2] += wv[o] * xa.z; acc[o][3] += wv[o] * xa.w;
                acc[o][4] += wv[o] * xb.x; acc[o][5] += wv[o] * xb.y;
                acc[o][6] += wv[o] * xb.z; acc[o][7] += wv[o] * xb.w;
            }
        }

        bool okA = (hw0 + pxA) < HW;
        bool okB = (hw0 + pxB) < HW;
        #pragma unroll
        for (int o = 0; o < 8; o++) {
            int oc = oc0 + ocl + o;
            float b = bias[oc];
            size_t obase = (size_t)(n * COUT + oc) * HW + hw0;
            if (okA) {
                float4 r;
                r.x = fqv(fmaxf(acc[o][0] + b, 0.0f), sact, 0.0f, 255.0f);
                r.y = fqv(fmaxf(acc[o][1] + b, 0.0f), sact, 0.0f, 255.0f);
                r.z = fqv(fmaxf(acc[o][2] + b, 0.0f), sact, 0.0f, 255.0f);
                r.w = fqv(fmaxf(acc[o][3] + b, 0.0f), sact, 0.0f, 255.0f);
                *(float4*)&out[obase + pxA] = r;
            }
            if (okB) {
                float4 r;
                r.x = fqv(fmaxf(acc[o][4] + b, 0.0f), sact, 0.0f, 255.0f);
                r.y = fqv(fmaxf(acc[o][5] + b, 0.0f), sact, 0.0f, 255.0f);
                r.z = fqv(fmaxf(acc[o][6] + b, 0.0f), sact, 0.0f, 255.0f);
                r.w = fqv(fmaxf(acc[o][7] + b, 0.0f), sact, 0.0f, 255.0f);
                *(float4*)&out[obase + pxB] = r;
            }
        }
    }
}

// ---------------------------------------------------------------------------
// 2x2 maxpool stride 2 + fq(int8). 2 outputs / thread, float4 row loads.
// ---------------------------------------------------------------------------
__global__ void pool_kernel(const float* __restrict__ in, float* __restrict__ out,
                            int C, int H, int W,
                            const float* __restrict__ scales, int si) {
    int OH = H >> 1, OW = W >> 1, OW2 = OW >> 1;
    int idx = blockIdx.x * 256 + threadIdx.x;
    int ox = (idx % OW2) * 2;
    int t = idx / OW2;
    int oy = t % OH; t /= OH;
    int c = t % C;
    int n = t / C;
    const float* ip = in + ((size_t)(n * C + c) * H + oy * 2) * W + ox * 2;
    float4 a = *(const float4*)ip;
    float4 b = *(const float4*)(ip + W);
    float s = scales[si];
    float2 r;
    r.x = fqv(fmaxf(fmaxf(a.x, a.y), fmaxf(b.x, b.y)), s, -128.0f, 127.0f);
    r.y = fqv(fmaxf(fmaxf(a.z, a.w), fmaxf(b.z, b.w)), s, -128.0f, 127.0f);
    *(float2*)&out[(size_t)idx * 2] = r;
}

// ---------------------------------------------------------------------------
// Global avg pool over 28x28 + fq(int8) -> g_gap. One block per (n,c).
// ---------------------------------------------------------------------------
__global__ void gap_kernel(const float* __restrict__ in,
                           const float* __restrict__ scales) {
    __shared__ float red[128];
    int bc = blockIdx.x;  // n*256 + c
    const float* ip = in + (size_t)bc * 784;
    float sum = 0.0f;
    for (int i = threadIdx.x; i < 784; i += 128) sum += ip[i];
    red[threadIdx.x] = sum;
    __syncthreads();
    for (int s = 64; s > 0; s >>= 1) {
        if (threadIdx.x < s) red[threadIdx.x] += red[threadIdx.x + s];
        __syncthreads();
    }
    if (threadIdx.x == 0)
        g_gap[bc] = fqv(red[0] * (1.0f / 784.0f), scales[11], -128.0f, 127.0f);
}

// ---------------------------------------------------------------------------
// FC: [8,256] @ Wq^T + b -> [8,10]
// ---------------------------------------------------------------------------
__global__ void fc_kernel(const float* __restrict__ fc_b, float* __restrict__ out) {
    int t = threadIdx.x;
    if (t < 80) {
        int n = t / 10, k = t % 10;
        float acc = fc_b[k];
        const float* w = g_wq + WQ_FC + k * 256;
        const float* g = g_gap + n * 256;
        #pragma unroll 8
        for (int i = 0; i < 256; i++) acc += w[i] * g[i];
        out[t] = acc;
    }
}

// ---------------------------------------------------------------------------
// Launch
// ---------------------------------------------------------------------------
extern "C" void kernel_launch(void* const* d_in, const int* in_sizes, int n_in,
                              void* d_out, int out_size) {
    const float* x       = (const float*)d_in[0];
    const float* scales  = (const float*)d_in[1];
    const float* conv1_w = (const float*)d_in[2];
    const float* conv1_b = (const float*)d_in[3];
    const float* b1_dw_w = (const float*)d_in[4];
    const float* b1_dw_b = (const float*)d_in[5];
    const float* b1_pw_w = (const float*)d_in[6];
    const float* b1_pw_b = (const float*)d_in[7];
    const float* b2_dw_w = (const float*)d_in[8];
    const float* b2_dw_b = (const float*)d_in[9];
    const float* b2_pw_w = (const float*)d_in[10];
    const float* b2_pw_b = (const float*)d_in[11];
    const float* b3_dw_w = (const float*)d_in[12];
    const float* b3_dw_b = (const float*)d_in[13];
    const float* b3_pw_w = (const float*)d_in[14];
    const float* b3_pw_b = (const float*)d_in[15];
    const float* fc_w    = (const float*)d_in[16];
    const float* fc_b    = (const float*)d_in[17];
    float* out = (float*)d_out;

    float *pA = nullptr, *pB = nullptr;
    cudaGetSymbolAddress((void**)&pA, g_bufA);
    cudaGetSymbolAddress((void**)&pB, g_bufB);

    // raise dynamic smem limits (s_x + s_w)
    cudaFuncSetAttribute(pw_kernel<64, 64>,
                         cudaFuncAttributeMaxDynamicSharedMemorySize, 81920);
    cudaFuncSetAttribute(pw_kernel<64, 128>,
                         cudaFuncAttributeMaxDynamicSharedMemorySize, 81920);
    cudaFuncSetAttribute(pw_kernel<128, 256>,
                         cudaFuncAttributeMaxDynamicSharedMemorySize, 163840);

    // 1) quantize all weights
    wq_kernel<<<8, 256>>>(conv1_w, b1_dw_w, b1_pw_w, b2_dw_w,
                          b2_pw_w, b3_dw_w, b3_pw_w, fc_w);

    // 2) conv1 (+input fq, relu, fq s1) -> A
    {
        dim3 cb(8, 32), cg(7, 7, 8);
        conv1_kernel<<<cg, cb>>>(x, conv1_b, scales, pA);
    }

    // block 1 @ 224x224, C=64   (HW=50176, 196 tiles of 256 px)
    dw_kernel<<<25088, 256>>>(pA, pB, WQ_B1DW, b1_dw_b, 64, 224, 224, scales, 2);
    pw_kernel<64, 64><<<dim3(196, 8), 256, 81920>>>(pB, pA, WQ_B1PW, b1_pw_b, 50176, scales, 3);
    pool_kernel<<<12544, 256>>>(pA, pB, 64, 224, 224, scales, 4);

    // block 2 @ 112x112, 64 -> 128  (HW=12544, 49 tiles)
    dw_kernel<<<6272, 256>>>(pB, pA, WQ_B2DW, b2_dw_b, 64, 112, 112, scales, 5);
    pw_kernel<64, 128><<<dim3(49, 8), 256, 81920>>>(pA, pB, WQ_B2PW, b2_pw_b, 12544, scales, 6);
    pool_kernel<<<6272, 256>>>(pB, pA, 128, 112, 112, scales, 7);

    // block 3 @ 56x56, 128 -> 256  (HW=3136, 13 tiles w/ guard)
    dw_kernel<<<3136, 256>>>(pA, pB, WQ_B3DW, b3_dw_b, 128, 56, 56, scales, 8);
    pw_kernel<128, 256><<<dim3(13, 8), 256, 163840>>>(pB, pA, WQ_B3PW, b3_pw_b, 3136, scales, 9);
    pool_kernel<<<3136, 256>>>(pA, pB, 256, 56, 56, scales, 10);

    // head
    gap_kernel<<<2048, 128>>>(pB, scales);
    fc_kernel<<<1, 128>>>(fc_b, out);
}

// round 4
// speedup vs baseline: 2.9997x; 2.5230x over previous
#include <cuda_runtime.h>
#include <cuda_bf16.h>

// ---------------------------------------------------------------------------
// Scratch (allocation-free: __device__ globals)
// Activations live as packed int8 in N[C/4]HW[4c] layout (one u32 = 4 channels
// of one pixel). u8 after ReLU-fq stages, s8 after pool-fq stages.
// ---------------------------------------------------------------------------
__device__ unsigned g_bufA[8 * 1024 * 1024];   // 32 MB ping (u32 words)
__device__ unsigned g_bufB[8 * 1024 * 1024];   // 32 MB pong
__device__ signed char g_wqi[52000];           // quantized int8 weights arena
__device__ unsigned g_wpk[11264];              // packed pw weights [ic4][oc] u32
__device__ float g_wscale[8];                  // per-tensor weight scales
__device__ float g_gap[2048];                  // [8,256] pooled features (float)

// byte-arena offsets (same order as wq srcs)
#define WQ_CONV1 0
#define WQ_B1DW  1728
#define WQ_B1PW  2304
#define WQ_B2DW  6400
#define WQ_B2PW  6976
#define WQ_B3DW  15168
#define WQ_B3PW  16320
#define WQ_FC    49088
// packed pw offsets (u32 units)
#define WP_B1PW  0
#define WP_B2PW  1024
#define WP_B3PW  3072

__device__ __forceinline__ float fqv(float x, float s, float lo, float hi) {
    float q = rintf(x / s);
    q = fminf(fmaxf(q, lo), hi);
    return q * s;
}

__device__ __forceinline__ void dp4a_us(int& acc, unsigned a, unsigned b) {
    asm("dp4a.u32.s32 %0, %1, %2, %3;" : "=r"(acc) : "r"(a), "r"(b), "r"(acc));
}

__device__ __forceinline__ int clampi(int v, int lo, int hi) {
    return min(max(v, lo), hi);
}

// ---------------------------------------------------------------------------
// Weight quantize: int8 arena + packed pw u32 + scales. One block per tensor.
// ---------------------------------------------------------------------------
__global__ void wq_kernel(const float* w0, const float* w1, const float* w2,
                          const float* w3, const float* w4, const float* w5,
                          const float* w6, const float* w7) {
    __shared__ float red[256];
    __shared__ signed char sq[32768];
    const float* srcs[8] = {w0, w1, w2, w3, w4, w5, w6, w7};
    const int sizes[8] = {1728, 576, 4096, 576, 8192, 1152, 32768, 2560};
    const int offs[8]  = {WQ_CONV1, WQ_B1DW, WQ_B1PW, WQ_B2DW,
                          WQ_B2PW, WQ_B3DW, WQ_B3PW, WQ_FC};
    const int cins[8]  = {0, 0, 64, 0, 64, 0, 128, 0};
    const int pwo[8]   = {-1, -1, WP_B1PW, -1, WP_B2PW, -1, WP_B3PW, -1};
    int t = blockIdx.x;
    const float* w = srcs[t];
    int n = sizes[t];

    float m = 0.0f;
    for (int i = threadIdx.x; i < n; i += 256) m = fmaxf(m, fabsf(w[i]));
    red[threadIdx.x] = m;
    __syncthreads();
    for (int s = 128; s > 0; s >>= 1) {
        if (threadIdx.x < s)
            red[threadIdx.x] = fmaxf(red[threadIdx.x], red[threadIdx.x + s]);
        __syncthreads();
    }
    float scale = red[0] / 127.0f;
    for (int i = threadIdx.x; i < n; i += 256) {
        int q = clampi(__float2int_rn(w[i] / scale), -127, 127);
        sq[i] = (signed char)q;
        g_wqi[offs[t] + i] = (signed char)q;
    }
    if (threadIdx.x == 0) g_wscale[t] = scale;
    __syncthreads();

    if (pwo[t] >= 0) {
        int CIN = cins[t], COUT = n / CIN;
        int npk = n / 4;
        for (int i = threadIdx.x; i < npk; i += 256) {
            int ic4 = i / COUT, oc = i % COUT;
            unsigned b0 = (unsigned char)sq[oc * CIN + ic4 * 4 + 0];
            unsigned b1 = (unsigned char)sq[oc * CIN + ic4 * 4 + 1];
            unsigned b2 = (unsigned char)sq[oc * CIN + ic4 * 4 + 2];
            unsigned b3 = (unsigned char)sq[oc * CIN + ic4 * 4 + 3];
            g_wpk[pwo[t] + i] = b0 | (b1 << 8) | (b2 << 16) | (b3 << 24);
        }
    }
}

// ---------------------------------------------------------------------------
// conv1: fq(x,s0,int8) -> 3x3 conv (3->64,pad1)+bias -> relu -> fq(s1,u8 bytes)
// Block (8,32): 32x32 tile, 4 px/thread, float math, packed u8 output.
// ---------------------------------------------------------------------------
__global__ void conv1_kernel(const float* __restrict__ x,
                             const float* __restrict__ bias,
                             const float* __restrict__ scales,
                             unsigned* __restrict__ out) {
    __shared__ float s_in[3][34][34];
    __shared__ float s_wf[1728];
    int n = blockIdx.z;
    int x0 = blockIdx.x * 32, y0 = blockIdx.y * 32;
    int tid = threadIdx.y * 8 + threadIdx.x;
    float s0 = scales[0];
    float inv_s1 = 1.0f / scales[1];
    float ws0 = g_wscale[0];

    for (int i = tid; i < 1728; i += 256)
        s_wf[i] = (float)g_wqi[WQ_CONV1 + i] * ws0;

    for (int i = tid; i < 3 * 34 * 34; i += 256) {
        int c = i / 1156;
        int r = i % 1156;
        int ly = r / 34, lx = r % 34;
        int gy = y0 + ly - 1, gx = x0 + lx - 1;
        float v = 0.0f;
        if (gy >= 0 && gy < 224 && gx >= 0 && gx < 224)
            v = fqv(x[((n * 3 + c) * 224 + gy) * 224 + gx], s0, -128.0f, 127.0f);
        s_in[c][ly][lx] = v;
    }
    __syncthreads();

    int tx = threadIdx.x, ty = threadIdx.y;
    int x4 = tx * 4;

    float vin[3][3][6];
    #pragma unroll
    for (int c = 0; c < 3; c++)
        #pragma unroll
        for (int ky = 0; ky < 3; ky++)
            #pragma unroll
            for (int dx = 0; dx < 6; dx++)
                vin[c][ky][dx] = s_in[c][ty + ky][x4 + dx];

    for (int ocg = 0; ocg < 16; ocg++) {
        float acc[4][4];   // [oc-in-group][px]
        #pragma unroll
        for (int j = 0; j < 4; j++) {
            float b = bias[ocg * 4 + j];
            acc[j][0] = b; acc[j][1] = b; acc[j][2] = b; acc[j][3] = b;
        }
        #pragma unroll
        for (int j = 0; j < 4; j++) {
            const float* wp = &s_wf[(ocg * 4 + j) * 27];
            #pragma unroll
            for (int c = 0; c < 3; c++)
                #pragma unroll
                for (int ky = 0; ky < 3; ky++)
                    #pragma unroll
                    for (int kx = 0; kx < 3; kx++) {
                        float w = wp[c * 9 + ky * 3 + kx];
                        acc[j][0] += vin[c][ky][kx + 0] * w;
                        acc[j][1] += vin[c][ky][kx + 1] * w;
                        acc[j][2] += vin[c][ky][kx + 2] * w;
                        acc[j][3] += vin[c][ky][kx + 3] * w;
                    }
        }
        uint4 pk;
        unsigned* pw = &pk.x;
        #pragma unroll
        for (int p = 0; p < 4; p++) {
            unsigned v = 0;
            #pragma unroll
            for (int j = 0; j < 4; j++) {
                int q = clampi(__float2int_rn(acc[j][p] * inv_s1), 0, 255);
                v |= (unsigned)q << (8 * j);
            }
            pw[p] = v;
        }
        size_t o = ((size_t)(n * 16 + ocg) * 224 + (y0 + ty)) * 224 + x0 + x4;
        *(uint4*)&out[o] = pk;
    }
}

// ---------------------------------------------------------------------------
// Depthwise 3x3 (pad 1) + bias + relu + fq(u8). Integer MACs on packed bytes.
// Thread: 4 px x 4 channels (one channel group).
// ---------------------------------------------------------------------------
template <bool SIGNED>
__global__ void dw_kernel(const unsigned* __restrict__ in,
                          unsigned* __restrict__ out,
                          int woff, const float* __restrict__ bias,
                          int G, int H, int W,
                          const float* __restrict__ scales,
                          int si_in, int si_out, int wsi) {
    extern __shared__ int s_wi[];  // [G*4][9]
    int tid = threadIdx.x;
    for (int i = tid; i < G * 36; i += 256) s_wi[i] = (int)g_wqi[woff + i];
    __syncthreads();

    int idx = blockIdx.x * 256 + tid;
    int W4 = W >> 2;
    int x4 = (idx % W4) * 4;
    int t = idx / W4;
    int yy = t % H; t /= H;
    int g = t % G;
    int n = t / G;

    int w[4][9];
    #pragma unroll
    for (int j = 0; j < 4; j++)
        #pragma unroll
        for (int k = 0; k < 9; k++) w[j][k] = s_wi[(g * 4 + j) * 9 + k];

    const unsigned* p = in + (size_t)(n * G + g) * H * W;
    int acc[4][4] = {};   // [px][ch]

    #pragma unroll
    for (int ky = 0; ky < 3; ky++) {
        int gy = yy + ky - 1;
        if (gy < 0 || gy >= H) continue;
        const unsigned* rp = p + (size_t)gy * W;
        uint4 mm = *(const uint4*)&rp[x4];
        unsigned v[6];
        v[0] = (x4 > 0) ? rp[x4 - 1] : 0u;
        v[1] = mm.x; v[2] = mm.y; v[3] = mm.z; v[4] = mm.w;
        v[5] = (x4 + 4 < W) ? rp[x4 + 4] : 0u;
        #pragma unroll
        for (int j = 0; j < 4; j++) {
            int b[6];
            #pragma unroll
            for (int d = 0; d < 6; d++) {
                if (SIGNED)
                    b[d] = (int)(v[d] << ((3 - j) * 8)) >> 24;
                else
                    b[d] = (int)((v[d] >> (j * 8)) & 0xFF);
            }
            #pragma unroll
            for (int pp = 0; pp < 4; pp++)
                acc[pp][j] += b[pp] * w[j][ky * 3 + 0]
                            + b[pp + 1] * w[j][ky * 3 + 1]
                            + b[pp + 2] * w[j][ky * 3 + 2];
        }
    }

    float inv_o = 1.0f / scales[si_out];
    float A = scales[si_in] * g_wscale[wsi] * inv_o;
    float B[4];
    #pragma unroll
    for (int j = 0; j < 4; j++) B[j] = bias[g * 4 + j] * inv_o;

    uint4 pk;
    unsigned* pw = &pk.x;
    #pragma unroll
    for (int pp = 0; pp < 4; pp++) {
        unsigned v = 0;
        #pragma unroll
        for (int j = 0; j < 4; j++) {
            int q = clampi(__float2int_rn(fmaf(A, (float)acc[pp][j], B[j])), 0, 255);
            v |= (unsigned)q << (8 * j);
        }
        pw[pp] = v;
    }
    *(uint4*)&out[(size_t)idx * 4] = pk;
}

// ---------------------------------------------------------------------------
// Pointwise 1x1 (CIN->COUT) via dp4a + bias + relu + fq(u8).
// Block tile: 256 px x 64 oc; thread 8 px x 8 oc; contraction packed 4 ic/u32.
// ---------------------------------------------------------------------------
template <int CIN, int COUT>
__global__ void __launch_bounds__(256)
pw_kernel(const unsigned* __restrict__ in, unsigned* __restrict__ out,
          int wpko, const float* __restrict__ bias,
          int HW, const float* __restrict__ scales,
          int si_in, int si_out, int wsi) {
    constexpr int CIN4 = CIN / 4;
    extern __shared__ unsigned pwsmem[];
    unsigned* s_x = pwsmem;               // [CIN4][256]
    unsigned* s_w = pwsmem + CIN4 * 256;  // [CIN4][64]
    int tid = threadIdx.x;
    int n = blockIdx.y;
    int hw0 = blockIdx.x * 256;

    for (int e = tid * 4; e < CIN4 * 256; e += 1024) {
        int ic4 = e >> 8, pix = e & 255;
        *(uint4*)&s_x[e] =
            *(const uint4*)&in[(size_t)(n * CIN4 + ic4) * HW + hw0 + pix];
    }

    float inv_o = 1.0f / scales[si_out];
    float A = scales[si_in] * g_wscale[wsi] * inv_o;
    int pxA = (tid & 31) * 4;
    int pxB = 128 + pxA;
    int ocl = (tid >> 5) * 8;

    bool okA = (hw0 + pxA) < HW;
    bool okB = (hw0 + pxB) < HW;

    for (int oc0 = 0; oc0 < COUT; oc0 += 64) {
        __syncthreads();
        for (int e = tid; e < CIN4 * 64; e += 256) {
            int ic4 = e >> 6, o = e & 63;
            s_w[e] = g_wpk[wpko + ic4 * COUT + oc0 + o];
        }
        __syncthreads();

        int acc[8][8] = {};
        #pragma unroll 4
        for (int ic4 = 0; ic4 < CIN4; ic4++) {
            uint4 xa = *(const uint4*)&s_x[ic4 * 256 + pxA];
            uint4 xb = *(const uint4*)&s_x[ic4 * 256 + pxB];
            uint4 wA = *(const uint4*)&s_w[ic4 * 64 + ocl];
            uint4 wB = *(const uint4*)&s_w[ic4 * 64 + ocl + 4];
            unsigned xs[8] = {xa.x, xa.y, xa.z, xa.w, xb.x, xb.y, xb.z, xb.w};
            unsigned ws8[8] = {wA.x, wA.y, wA.z, wA.w, wB.x, wB.y, wB.z, wB.w};
            #pragma unroll
            for (int o = 0; o < 8; o++)
                #pragma unroll
                for (int p = 0; p < 8; p++)
                    dp4a_us(acc[o][p], xs[p], ws8[o]);
        }

        #pragma unroll
        for (int og = 0; og < 2; og++) {
            float B[4];
            #pragma unroll
            for (int j = 0; j < 4; j++)
                B[j] = bias[oc0 + ocl + og * 4 + j] * inv_o;
            int oc4 = (oc0 + ocl) / 4 + og;
            size_t obase = (size_t)(n * (COUT / 4) + oc4) * HW + hw0;
            if (okA) {
                uint4 pk;
                unsigned* pw = &pk.x;
                #pragma unroll
                for (int p = 0; p < 4; p++) {
                    unsigned v = 0;
                    #pragma unroll
                    for (int j = 0; j < 4; j++) {
                        int q = clampi(__float2int_rn(
                            fmaf(A, (float)acc[og * 4 + j][p], B[j])), 0, 255);
                        v |= (unsigned)q << (8 * j);
                    }
                    pw[p] = v;
                }
                *(uint4*)&out[obase + pxA] = pk;
            }
            if (okB) {
                uint4 pk;
                unsigned* pw = &pk.x;
                #pragma unroll
                for (int p = 0; p < 4; p++) {
                    unsigned v = 0;
                    #pragma unroll
                    for (int j = 0; j < 4; j++) {
                        int q = clampi(__float2int_rn(
                            fmaf(A, (float)acc[og * 4 + j][p + 4], B[j])), 0, 255);
                        v |= (unsigned)q << (8 * j);
                    }
                    pw[p] = v;
                }
                *(uint4*)&out[obase + pxB] = pk;
            }
        }
    }
}

// ---------------------------------------------------------------------------
// 2x2 maxpool stride 2 (per-byte vmax on u8) + requant to s8.
// Thread: 2 output px (one channel group).
// ---------------------------------------------------------------------------
__global__ void pool_kernel(const unsigned* __restrict__ in,
                            unsigned* __restrict__ out,
                            int G, int H, int W,
                            const float* __restrict__ scales,
                            int si_in, int si_out) {
    int OH = H >> 1, OW = W >> 1, OW2 = OW >> 1;
    int idx = blockIdx.x * 256 + threadIdx.x;
    int ox = (idx % OW2) * 2;
    int t = idx / OW2;
    int oy = t % OH; t /= OH;
    int g = t % G;
    int n = t / G;

    const unsigned* p = in + ((size_t)(n * G + g) * H + oy * 2) * W + ox * 2;
    uint4 a = *(const uint4*)p;
    uint4 b = *(const uint4*)(p + W);
    unsigned m0 = __vmaxu4(__vmaxu4(a.x, a.y), __vmaxu4(b.x, b.y));
    unsigned m1 = __vmaxu4(__vmaxu4(a.z, a.w), __vmaxu4(b.z, b.w));

    float r = scales[si_in] / scales[si_out];
    uint2 pk;
    unsigned mm[2] = {m0, m1};
    unsigned* pw = &pk.x;
    #pragma unroll
    for (int p2 = 0; p2 < 2; p2++) {
        unsigned v = 0;
        #pragma unroll
        for (int j = 0; j < 4; j++) {
            int byte = (int)((mm[p2] >> (8 * j)) & 0xFF);
            int q = clampi(__float2int_rn((float)byte * r), -128, 127);
            v |= (unsigned)(q & 0xFF) << (8 * j);
        }
        pw[p2] = v;
    }
    out[((size_t)(n * G + g) * OH + oy) * OW + ox] = pk.x;
    out[((size_t)(n * G + g) * OH + oy) * OW + ox + 1] = pk.y;
}

// ---------------------------------------------------------------------------
// Global avg pool 28x28 (s8 input) + fq(s[11], int8) -> g_gap floats.
// One block per (n, channel-group).
// ---------------------------------------------------------------------------
__global__ void gap_kernel(const unsigned* __restrict__ in,
                           const float* __restrict__ scales) {
    __shared__ int4 red[128];
    int bc = blockIdx.x;        // n*64 + g
    const unsigned* p = in + (size_t)bc * 784;
    int s0 = 0, s1 = 0, s2 = 0, s3 = 0;
    for (int i = threadIdx.x; i < 784; i += 128) {
        unsigned v = p[i];
        s0 += (int)(v << 24) >> 24;
        s1 += (int)(v << 16) >> 24;
        s2 += (int)(v << 8) >> 24;
        s3 += (int)v >> 24;
    }
    red[threadIdx.x] = make_int4(s0, s1, s2, s3);
    __syncthreads();
    for (int s = 64; s > 0; s >>= 1) {
        if (threadIdx.x < s) {
            int4 a = red[threadIdx.x], b = red[threadIdx.x + s];
            red[threadIdx.x] = make_int4(a.x + b.x, a.y + b.y, a.z + b.z, a.w + b.w);
        }
        __syncthreads();
    }
    if (threadIdx.x == 0) {
        float s10 = scales[10], s11 = scales[11];
        int4 r = red[0];
        int n = bc >> 6, g = bc & 63;
        int sums[4] = {r.x, r.y, r.z, r.w};
        #pragma unroll
        for (int j = 0; j < 4; j++) {
            float m = s10 * (float)sums[j] / 784.0f;
            g_gap[n * 256 + g * 4 + j] = fqv(m, s11, -128.0f, 127.0f);
        }
    }
}

// ---------------------------------------------------------------------------
// FC: [8,256] @ Wq^T + b -> [8,10]
// ---------------------------------------------------------------------------
__global__ void fc_kernel(const float* __restrict__ fc_b, float* __restrict__ out) {
    int t = threadIdx.x;
    if (t < 80) {
        int n = t / 10, k = t % 10;
        float ws = g_wscale[7];
        float acc = fc_b[k];
        const signed char* w = g_wqi + WQ_FC + k * 256;
        const float* g = g_gap + n * 256;
        #pragma unroll 8
        for (int i = 0; i < 256; i++) acc += (float)w[i] * ws * g[i];
        out[t] = acc;
    }
}

// ---------------------------------------------------------------------------
// Launch
// ---------------------------------------------------------------------------
extern "C" void kernel_launch(void* const* d_in, const int* in_sizes, int n_in,
                              void* d_out, int out_size) {
    const float* x       = (const float*)d_in[0];
    const float* scales  = (const float*)d_in[1];
    const float* conv1_w = (const float*)d_in[2];
    const float* conv1_b = (const float*)d_in[3];
    const float* b1_dw_w = (const float*)d_in[4];
    const float* b1_dw_b = (const float*)d_in[5];
    const float* b1_pw_w = (const float*)d_in[6];
    const float* b1_pw_b = (const float*)d_in[7];
    const float* b2_dw_w = (const float*)d_in[8];
    const float* b2_dw_b = (const float*)d_in[9];
    const float* b2_pw_w = (const float*)d_in[10];
    const float* b2_pw_b = (const float*)d_in[11];
    const float* b3_dw_w = (const float*)d_in[12];
    const float* b3_dw_b = (const float*)d_in[13];
    const float* b3_pw_w = (const float*)d_in[14];
    const float* b3_pw_b = (const float*)d_in[15];
    const float* fc_b    = (const float*)d_in[17];
    float* out = (float*)d_out;

    unsigned *pA = nullptr, *pB = nullptr;
    cudaGetSymbolAddress((void**)&pA, g_bufA);
    cudaGetSymbolAddress((void**)&pB, g_bufB);

    // 1) quantize weights (int8 arena + packed pw + scales)
    wq_kernel<<<8, 256>>>(conv1_w, b1_dw_w, b1_pw_w, b2_dw_w,
                          b2_pw_w, b3_dw_w, b3_pw_w, (const float*)d_in[16]);

    // 2) conv1 -> A (u8, N[16]HW[4])
    {
        dim3 cb(8, 32), cg(7, 7, 8);
        conv1_kernel<<<cg, cb>>>(x, conv1_b, scales, pA);
    }

    // block 1 @ 224x224, C=64 (G=16)
    dw_kernel<false><<<6272, 256, 16 * 36 * 4>>>(pA, pB, WQ_B1DW, b1_dw_b,
                                                 16, 224, 224, scales, 1, 2, 1);
    pw_kernel<64, 64><<<dim3(196, 8), 256, 20480>>>(pB, pA, WP_B1PW, b1_pw_b,
                                                    50176, scales, 2, 3, 2);
    pool_kernel<<<3136, 256>>>(pA, pB, 16, 224, 224, scales, 3, 4);

    // block 2 @ 112x112, 64 -> 128
    dw_kernel<true><<<1568, 256, 16 * 36 * 4>>>(pB, pA, WQ_B2DW, b2_dw_b,
                                                16, 112, 112, scales, 4, 5, 3);
    pw_kernel<64, 128><<<dim3(49, 8), 256, 20480>>>(pA, pB, WP_B2PW, b2_pw_b,
                                                    12544, scales, 5, 6, 4);
    pool_kernel<<<1568, 256>>>(pB, pA, 32, 112, 112, scales, 6, 7);

    // block 3 @ 56x56, 128 -> 256
    dw_kernel<true><<<784, 256, 32 * 36 * 4>>>(pA, pB, WQ_B3DW, b3_dw_b,
                                               32, 56, 56, scales, 7, 8, 5);
    pw_kernel<128, 256><<<dim3(13, 8), 256, 40960>>>(pB, pA, WP_B3PW, b3_pw_b,
                                                     3136, scales, 8, 9, 6);
    pool_kernel<<<784, 256>>>(pA, pB, 64, 56, 56, scales, 9, 10);

    // head
    gap_kernel<<<512, 128>>>(pB, scales);
    fc_kernel<<<1, 128>>>(fc_b, out);
}

// round 5
// speedup vs baseline: 3.3915x; 1.1306x over previous
#include <cuda_runtime.h>
#include <cuda_bf16.h>

// ---------------------------------------------------------------------------
// Scratch (allocation-free: __device__ globals)
// Activations live as packed int8 in N[C/4]HW[4c] layout (one u32 = 4 channels
// of one pixel). u8 after ReLU-fq stages, s8 after pool-fq stages.
// ---------------------------------------------------------------------------
__device__ unsigned g_bufA[8 * 1024 * 1024];   // 32 MB ping (u32 words)
__device__ unsigned g_bufB[8 * 1024 * 1024];   // 32 MB pong
__device__ signed char g_wqi[52000];           // quantized int8 weights arena
__device__ unsigned g_wpk[12288];              // packed weights (u32)
__device__ float g_wscale[8];                  // per-tensor weight scales
__device__ float g_gap[2048];                  // [8,256] pooled features (float)

// byte-arena offsets (same order as wq srcs)
#define WQ_CONV1 0
#define WQ_B1DW  1728
#define WQ_B1PW  2304
#define WQ_B2DW  6400
#define WQ_B2PW  6976
#define WQ_B3DW  15168
#define WQ_B3PW  16320
#define WQ_FC    49088
// packed offsets (u32 units)
#define WP_B1PW  0
#define WP_B2PW  1024
#define WP_B3PW  3072
#define WP_C1    11264

__device__ __forceinline__ float fqv(float x, float s, float lo, float hi) {
    float q = rintf(x / s);
    q = fminf(fmaxf(q, lo), hi);
    return q * s;
}

__device__ __forceinline__ void dp4a_us(int& acc, unsigned a, unsigned b) {
    asm("dp4a.u32.s32 %0, %1, %2, %3;" : "=r"(acc) : "r"(a), "r"(b), "r"(acc));
}
__device__ __forceinline__ void dp4a_ss(int& acc, unsigned a, unsigned b) {
    asm("dp4a.s32.s32 %0, %1, %2, %3;" : "=r"(acc) : "r"(a), "r"(b), "r"(acc));
}

__device__ __forceinline__ int clampi(int v, int lo, int hi) {
    return min(max(v, lo), hi);
}

// ---------------------------------------------------------------------------
// Weight quantize: int8 arena + packed pw/conv1 u32 + scales. One block/tensor.
// ---------------------------------------------------------------------------
__global__ void wq_kernel(const float* w0, const float* w1, const float* w2,
                          const float* w3, const float* w4, const float* w5,
                          const float* w6, const float* w7) {
    __shared__ float red[256];
    __shared__ signed char sq[32768];
    const float* srcs[8] = {w0, w1, w2, w3, w4, w5, w6, w7};
    const int sizes[8] = {1728, 576, 4096, 576, 8192, 1152, 32768, 2560};
    const int offs[8]  = {WQ_CONV1, WQ_B1DW, WQ_B1PW, WQ_B2DW,
                          WQ_B2PW, WQ_B3DW, WQ_B3PW, WQ_FC};
    const int cins[8]  = {0, 0, 64, 0, 64, 0, 128, 0};
    const int pwo[8]   = {-1, -1, WP_B1PW, -1, WP_B2PW, -1, WP_B3PW, -1};
    int t = blockIdx.x;
    const float* w = srcs[t];
    int n = sizes[t];

    float m = 0.0f;
    for (int i = threadIdx.x; i < n; i += 256) m = fmaxf(m, fabsf(w[i]));
    red[threadIdx.x] = m;
    __syncthreads();
    for (int s = 128; s > 0; s >>= 1) {
        if (threadIdx.x < s)
            red[threadIdx.x] = fmaxf(red[threadIdx.x], red[threadIdx.x + s]);
        __syncthreads();
    }
    float scale = red[0] / 127.0f;
    for (int i = threadIdx.x; i < n; i += 256) {
        int q = clampi(__float2int_rn(w[i] / scale), -127, 127);
        sq[i] = (signed char)q;
        g_wqi[offs[t] + i] = (signed char)q;
    }
    if (threadIdx.x == 0) g_wscale[t] = scale;
    __syncthreads();

    if (pwo[t] >= 0) {
        int CIN = cins[t], COUT = n / CIN;
        int npk = n / 4;
        for (int i = threadIdx.x; i < npk; i += 256) {
            int ic4 = i / COUT, oc = i % COUT;
            unsigned b0 = (unsigned char)sq[oc * CIN + ic4 * 4 + 0];
            unsigned b1 = (unsigned char)sq[oc * CIN + ic4 * 4 + 1];
            unsigned b2 = (unsigned char)sq[oc * CIN + ic4 * 4 + 2];
            unsigned b3 = (unsigned char)sq[oc * CIN + ic4 * 4 + 3];
            g_wpk[pwo[t] + i] = b0 | (b1 << 8) | (b2 << 16) | (b3 << 24);
        }
    }
    if (t == 0) {
        // conv1 pack: [oc][9 taps], bytes = [ic0, ic1, ic2, 0]
        for (int i = threadIdx.x; i < 576; i += 256) {
            int oc = i / 9, k = i % 9;
            unsigned b0 = (unsigned char)sq[oc * 27 + 0 + k];
            unsigned b1 = (unsigned char)sq[oc * 27 + 9 + k];
            unsigned b2 = (unsigned char)sq[oc * 27 + 18 + k];
            g_wpk[WP_C1 + i] = b0 | (b1 << 8) | (b2 << 16);
        }
    }
}

// ---------------------------------------------------------------------------
// Input quantize + pack: fq(x,s0,s8) -> [n][224*224] u32 of [c0,c1,c2,0].
// ---------------------------------------------------------------------------
__global__ void quant_input_kernel(const float* __restrict__ x,
                                   unsigned* __restrict__ out,
                                   const float* __restrict__ scales) {
    int idx = blockIdx.x * 256 + threadIdx.x;       // 100352 total
    int n = idx / 12544;
    int p4 = (idx % 12544) * 4;
    float inv_s0 = 1.0f / scales[0];
    const float* base = x + (size_t)n * 3 * 50176 + p4;
    float4 c0 = *(const float4*)(base);
    float4 c1 = *(const float4*)(base + 50176);
    float4 c2 = *(const float4*)(base + 100352);
    const float* f0 = &c0.x;
    const float* f1 = &c1.x;
    const float* f2 = &c2.x;
    uint4 pk;
    unsigned* pw = &pk.x;
    #pragma unroll
    for (int j = 0; j < 4; j++) {
        unsigned b0 = (unsigned)(clampi(__float2int_rn(f0[j] * inv_s0), -128, 127) & 0xFF);
        unsigned b1 = (unsigned)(clampi(__float2int_rn(f1[j] * inv_s0), -128, 127) & 0xFF);
        unsigned b2 = (unsigned)(clampi(__float2int_rn(f2[j] * inv_s0), -128, 127) & 0xFF);
        pw[j] = b0 | (b1 << 8) | (b2 << 16);
    }
    *(uint4*)&out[(size_t)n * 50176 + p4] = pk;
}

// ---------------------------------------------------------------------------
// conv1 (int): packed s8 input -> 3x3 conv (3->64, pad 1) via dp4a
// + bias + relu + fq(s1, u8 bytes). Block (8,32): 32x32 tile, 4 px/thread.
// ---------------------------------------------------------------------------
__global__ void conv1_kernel(const unsigned* __restrict__ xin,
                             const float* __restrict__ bias,
                             const float* __restrict__ scales,
                             unsigned* __restrict__ out) {
    __shared__ unsigned s_pix[34 * 34];
    __shared__ unsigned s_w[576];
    __shared__ float s_b[64];
    int n = blockIdx.z;
    int x0 = blockIdx.x * 32, y0 = blockIdx.y * 32;
    int tid = threadIdx.y * 8 + threadIdx.x;

    for (int i = tid; i < 576; i += 256) s_w[i] = g_wpk[WP_C1 + i];
    if (tid < 64) s_b[tid] = bias[tid];

    const unsigned* xp = xin + (size_t)n * 50176;
    for (int i = tid; i < 34 * 34; i += 256) {
        int ly = i / 34, lx = i % 34;
        int gy = y0 + ly - 1, gx = x0 + lx - 1;
        unsigned v = 0;
        if (gy >= 0 && gy < 224 && gx >= 0 && gx < 224)
            v = xp[gy * 224 + gx];
        s_pix[i] = v;
    }
    __syncthreads();

    int tx = threadIdx.x, ty = threadIdx.y;
    int x4 = tx * 4;

    unsigned p[3][6];
    #pragma unroll
    for (int ky = 0; ky < 3; ky++)
        #pragma unroll
        for (int dx = 0; dx < 6; dx++)
            p[ky][dx] = s_pix[(ty + ky) * 34 + x4 + dx];

    float inv_s1 = 1.0f / scales[1];
    float A = scales[0] * g_wscale[0] * inv_s1;
    size_t obase = ((size_t)(n * 16) * 224 + (y0 + ty)) * 224 + x0 + x4;

    for (int ocg = 0; ocg < 16; ocg++) {
        int acc[4][4] = {};   // [oc-in-group][px]
        #pragma unroll
        for (int j = 0; j < 4; j++) {
            const unsigned* wp = &s_w[(ocg * 4 + j) * 9];
            #pragma unroll
            for (int ky = 0; ky < 3; ky++)
                #pragma unroll
                for (int kx = 0; kx < 3; kx++) {
                    unsigned w = wp[ky * 3 + kx];
                    dp4a_ss(acc[j][0], p[ky][kx + 0], w);
                    dp4a_ss(acc[j][1], p[ky][kx + 1], w);
                    dp4a_ss(acc[j][2], p[ky][kx + 2], w);
                    dp4a_ss(acc[j][3], p[ky][kx + 3], w);
                }
        }
        uint4 pk;
        unsigned* pw = &pk.x;
        #pragma unroll
        for (int pt = 0; pt < 4; pt++) {
            unsigned v = 0;
            #pragma unroll
            for (int j = 0; j < 4; j++) {
                float B = s_b[ocg * 4 + j] * inv_s1;
                int q = clampi(__float2int_rn(fmaf(A, (float)acc[j][pt], B)), 0, 255);
                v |= (unsigned)q << (8 * j);
            }
            pw[pt] = v;
        }
        *(uint4*)&out[obase + (size_t)ocg * 50176] = pk;
    }
}

// ---------------------------------------------------------------------------
// Depthwise 3x3 (pad 1) + bias + relu + fq(u8). Integer MACs on packed bytes.
// Thread: 4 px x 4 channels (one channel group).
// ---------------------------------------------------------------------------
template <bool SIGNED>
__global__ void dw_kernel(const unsigned* __restrict__ in,
                          unsigned* __restrict__ out,
                          int woff, const float* __restrict__ bias,
                          int G, int H, int W,
                          const float* __restrict__ scales,
                          int si_in, int si_out, int wsi) {
    extern __shared__ int s_wi[];  // [G*4][9]
    int tid = threadIdx.x;
    for (int i = tid; i < G * 36; i += 256) s_wi[i] = (int)g_wqi[woff + i];
    __syncthreads();

    int idx = blockIdx.x * 256 + tid;
    int W4 = W >> 2;
    int x4 = (idx % W4) * 4;
    int t = idx / W4;
    int yy = t % H; t /= H;
    int g = t % G;
    int n = t / G;

    int w[4][9];
    #pragma unroll
    for (int j = 0; j < 4; j++)
        #pragma unroll
        for (int k = 0; k < 9; k++) w[j][k] = s_wi[(g * 4 + j) * 9 + k];

    const unsigned* p = in + (size_t)(n * G + g) * H * W;
    int acc[4][4] = {};   // [px][ch]

    #pragma unroll
    for (int ky = 0; ky < 3; ky++) {
        int gy = yy + ky - 1;
        if (gy < 0 || gy >= H) continue;
        const unsigned* rp = p + (size_t)gy * W;
        uint4 mm = *(const uint4*)&rp[x4];
        unsigned v[6];
        v[0] = (x4 > 0) ? rp[x4 - 1] : 0u;
        v[1] = mm.x; v[2] = mm.y; v[3] = mm.z; v[4] = mm.w;
        v[5] = (x4 + 4 < W) ? rp[x4 + 4] : 0u;
        #pragma unroll
        for (int j = 0; j < 4; j++) {
            int b[6];
            #pragma unroll
            for (int d = 0; d < 6; d++) {
                if (SIGNED)
                    b[d] = (int)(v[d] << ((3 - j) * 8)) >> 24;
                else
                    b[d] = (int)((v[d] >> (j * 8)) & 0xFF);
            }
            #pragma unroll
            for (int pp = 0; pp < 4; pp++)
                acc[pp][j] += b[pp] * w[j][ky * 3 + 0]
                            + b[pp + 1] * w[j][ky * 3 + 1]
                            + b[pp + 2] * w[j][ky * 3 + 2];
        }
    }

    float inv_o = 1.0f / scales[si_out];
    float A = scales[si_in] * g_wscale[wsi] * inv_o;
    float B[4];
    #pragma unroll
    for (int j = 0; j < 4; j++) B[j] = bias[g * 4 + j] * inv_o;

    uint4 pk;
    unsigned* pw = &pk.x;
    #pragma unroll
    for (int pp = 0; pp < 4; pp++) {
        unsigned v = 0;
        #pragma unroll
        for (int j = 0; j < 4; j++) {
            int q = clampi(__float2int_rn(fmaf(A, (float)acc[pp][j], B[j])), 0, 255);
            v |= (unsigned)q << (8 * j);
        }
        pw[pp] = v;
    }
    *(uint4*)&out[(size_t)idx * 4] = pk;
}

// ---------------------------------------------------------------------------
// Pointwise 1x1 (CIN->COUT) via dp4a + bias + relu + fq(u8).
// Block tile: 128 px x 64 oc; thread 4 px x 8 oc. Higher occupancy variant.
// ---------------------------------------------------------------------------
template <int CIN, int COUT>
__global__ void __launch_bounds__(256)
pw_kernel(const unsigned* __restrict__ in, unsigned* __restrict__ out,
          int wpko, const float* __restrict__ bias,
          int HW, const float* __restrict__ scales,
          int si_in, int si_out, int wsi) {
    constexpr int CIN4 = CIN / 4;
    __shared__ unsigned s_x[CIN4 * 128];
    __shared__ unsigned s_w[CIN4 * 64];
    int tid = threadIdx.x;
    int n = blockIdx.y;
    int hw0 = blockIdx.x * 128;

    for (int e = tid * 4; e < CIN4 * 128; e += 1024) {
        int ic4 = e >> 7, pix = e & 127;
        *(uint4*)&s_x[e] =
            *(const uint4*)&in[(size_t)(n * CIN4 + ic4) * HW + hw0 + pix];
    }

    float inv_o = 1.0f / scales[si_out];
    float A = scales[si_in] * g_wscale[wsi] * inv_o;
    int pxA = (tid & 31) * 4;
    int ocl = (tid >> 5) * 8;
    bool ok = (hw0 + pxA) < HW;

    for (int oc0 = 0; oc0 < COUT; oc0 += 64) {
        __syncthreads();
        for (int e = tid; e < CIN4 * 64; e += 256) {
            int ic4 = e >> 6, o = e & 63;
            s_w[e] = g_wpk[wpko + ic4 * COUT + oc0 + o];
        }
        __syncthreads();

        int acc[8][4] = {};
        #pragma unroll 4
        for (int ic4 = 0; ic4 < CIN4; ic4++) {
            uint4 xa = *(const uint4*)&s_x[ic4 * 128 + pxA];
            uint4 wA = *(const uint4*)&s_w[ic4 * 64 + ocl];
            uint4 wB = *(const uint4*)&s_w[ic4 * 64 + ocl + 4];
            unsigned ws8[8] = {wA.x, wA.y, wA.z, wA.w, wB.x, wB.y, wB.z, wB.w};
            #pragma unroll
            for (int o = 0; o < 8; o++) {
                dp4a_us(acc[o][0], xa.x, ws8[o]);
                dp4a_us(acc[o][1], xa.y, ws8[o]);
                dp4a_us(acc[o][2], xa.z, ws8[o]);
                dp4a_us(acc[o][3], xa.w, ws8[o]);
            }
        }

        if (ok) {
            #pragma unroll
            for (int og = 0; og < 2; og++) {
                float B[4];
                #pragma unroll
                for (int j = 0; j < 4; j++)
                    B[j] = bias[oc0 + ocl + og * 4 + j] * inv_o;
                int oc4 = (oc0 + ocl) / 4 + og;
                size_t obase = (size_t)(n * (COUT / 4) + oc4) * HW + hw0;
                uint4 pk;
                unsigned* pw = &pk.x;
                #pragma unroll
                for (int pt = 0; pt < 4; pt++) {
                    unsigned v = 0;
                    #pragma unroll
                    for (int j = 0; j < 4; j++) {
                        int q = clampi(__float2int_rn(
                            fmaf(A, (float)acc[og * 4 + j][pt], B[j])), 0, 255);
                        v |= (unsigned)q << (8 * j);
                    }
                    pw[pt] = v;
                }
                *(uint4*)&out[obase + pxA] = pk;
            }
        }
    }
}

// ---------------------------------------------------------------------------
// 2x2 maxpool stride 2 (per-byte vmax on u8) + requant to s8.
// Thread: 2 output px (one channel group).
// ---------------------------------------------------------------------------
__global__ void pool_kernel(const unsigned* __restrict__ in,
                            unsigned* __restrict__ out,
                            int G, int H, int W,
                            const float* __restrict__ scales,
                            int si_in, int si_out) {
    int OH = H >> 1, OW = W >> 1, OW2 = OW >> 1;
    int idx = blockIdx.x * 256 + threadIdx.x;
    int ox = (idx % OW2) * 2;
    int t = idx / OW2;
    int oy = t % OH; t /= OH;
    int g = t % G;
    int n = t / G;

    const unsigned* p = in + ((size_t)(n * G + g) * H + oy * 2) * W + ox * 2;
    uint4 a = *(const uint4*)p;
    uint4 b = *(const uint4*)(p + W);
    unsigned m0 = __vmaxu4(__vmaxu4(a.x, a.y), __vmaxu4(b.x, b.y));
    unsigned m1 = __vmaxu4(__vmaxu4(a.z, a.w), __vmaxu4(b.z, b.w));

    float r = scales[si_in] / scales[si_out];
    uint2 pk;
    unsigned mm[2] = {m0, m1};
    unsigned* pw = &pk.x;
    #pragma unroll
    for (int p2 = 0; p2 < 2; p2++) {
        unsigned v = 0;
        #pragma unroll
        for (int j = 0; j < 4; j++) {
            int byte = (int)((mm[p2] >> (8 * j)) & 0xFF);
            int q = clampi(__float2int_rn((float)byte * r), -128, 127);
            v |= (unsigned)(q & 0xFF) << (8 * j);
        }
        pw[p2] = v;
    }
    out[((size_t)(n * G + g) * OH + oy) * OW + ox] = pk.x;
    out[((size_t)(n * G + g) * OH + oy) * OW + ox + 1] = pk.y;
}

// ---------------------------------------------------------------------------
// Global avg pool 28x28 (s8 input) + fq(s[11], int8) -> g_gap floats.
// ---------------------------------------------------------------------------
__global__ void gap_kernel(const unsigned* __restrict__ in,
                           const float* __restrict__ scales) {
    __shared__ int4 red[128];
    int bc = blockIdx.x;        // n*64 + g
    const unsigned* p = in + (size_t)bc * 784;
    int s0 = 0, s1 = 0, s2 = 0, s3 = 0;
    for (int i = threadIdx.x; i < 784; i += 128) {
        unsigned v = p[i];
        s0 += (int)(v << 24) >> 24;
        s1 += (int)(v << 16) >> 24;
        s2 += (int)(v << 8) >> 24;
        s3 += (int)v >> 24;
    }
    red[threadIdx.x] = make_int4(s0, s1, s2, s3);
    __syncthreads();
    for (int s = 64; s > 0; s >>= 1) {
        if (threadIdx.x < s) {
            int4 a = red[threadIdx.x], b = red[threadIdx.x + s];
            red[threadIdx.x] = make_int4(a.x + b.x, a.y + b.y, a.z + b.z, a.w + b.w);
        }
        __syncthreads();
    }
    if (threadIdx.x == 0) {
        float s10 = scales[10], s11 = scales[11];
        int4 r = red[0];
        int n = bc >> 6, g = bc & 63;
        int sums[4] = {r.x, r.y, r.z, r.w};
        #pragma unroll
        for (int j = 0; j < 4; j++) {
            float m = s10 * (float)sums[j] / 784.0f;
            g_gap[n * 256 + g * 4 + j] = fqv(m, s11, -128.0f, 127.0f);
        }
    }
}

// ---------------------------------------------------------------------------
// FC: [8,256] @ Wq^T + b -> [8,10]
// ---------------------------------------------------------------------------
__global__ void fc_kernel(const float* __restrict__ fc_b, float* __restrict__ out) {
    int t = threadIdx.x;
    if (t < 80) {
        int n = t / 10, k = t % 10;
        float ws = g_wscale[7];
        float acc = fc_b[k];
        const signed char* w = g_wqi + WQ_FC + k * 256;
        const float* g = g_gap + n * 256;
        #pragma unroll 8
        for (int i = 0; i < 256; i++) acc += (float)w[i] * ws * g[i];
        out[t] = acc;
    }
}

// ---------------------------------------------------------------------------
// Launch
// ---------------------------------------------------------------------------
extern "C" void kernel_launch(void* const* d_in, const int* in_sizes, int n_in,
                              void* d_out, int out_size) {
    const float* x       = (const float*)d_in[0];
    const float* scales  = (const float*)d_in[1];
    const float* conv1_w = (const float*)d_in[2];
    const float* conv1_b = (const float*)d_in[3];
    const float* b1_dw_w = (const float*)d_in[4];
    const float* b1_dw_b = (const float*)d_in[5];
    const float* b1_pw_w = (const float*)d_in[6];
    const float* b1_pw_b = (const float*)d_in[7];
    const float* b2_dw_w = (const float*)d_in[8];
    const float* b2_dw_b = (const float*)d_in[9];
    const float* b2_pw_w = (const float*)d_in[10];
    const float* b2_pw_b = (const float*)d_in[11];
    const float* b3_dw_w = (const float*)d_in[12];
    const float* b3_dw_b = (const float*)d_in[13];
    const float* b3_pw_w = (const float*)d_in[14];
    const float* b3_pw_b = (const float*)d_in[15];
    const float* fc_b    = (const float*)d_in[17];
    float* out = (float*)d_out;

    unsigned *pA = nullptr, *pB = nullptr;
    cudaGetSymbolAddress((void**)&pA, g_bufA);
    cudaGetSymbolAddress((void**)&pB, g_bufB);

    // 1) quantize weights (int8 arena + packed + scales)
    wq_kernel<<<8, 256>>>(conv1_w, b1_dw_w, b1_pw_w, b2_dw_w,
                          b2_pw_w, b3_dw_w, b3_pw_w, (const float*)d_in[16]);

    // 2) quantize + pack input -> B;  conv1 (int) -> A (u8, N[16]HW[4])
    quant_input_kernel<<<392, 256>>>(x, pB, scales);
    {
        dim3 cb(8, 32), cg(7, 7, 8);
        conv1_kernel<<<cg, cb>>>(pB, conv1_b, scales, pA);
    }

    // block 1 @ 224x224, C=64 (G=16)
    dw_kernel<false><<<6272, 256, 16 * 36 * 4>>>(pA, pB, WQ_B1DW, b1_dw_b,
                                                 16, 224, 224, scales, 1, 2, 1);
    pw_kernel<64, 64><<<dim3(392, 8), 256>>>(pB, pA, WP_B1PW, b1_pw_b,
                                             50176, scales, 2, 3, 2);
    pool_kernel<<<3136, 256>>>(pA, pB, 16, 224, 224, scales, 3, 4);

    // block 2 @ 112x112, 64 -> 128
    dw_kernel<true><<<1568, 256, 16 * 36 * 4>>>(pB, pA, WQ_B2DW, b2_dw_b,
                                                16, 112, 112, scales, 4, 5, 3);
    pw_kernel<64, 128><<<dim3(98, 8), 256>>>(pA, pB, WP_B2PW, b2_pw_b,
                                             12544, scales, 5, 6, 4);
    pool_kernel<<<1568, 256>>>(pB, pA, 32, 112, 112, scales, 6, 7);

    // block 3 @ 56x56, 128 -> 256
    dw_kernel<true><<<784, 256, 32 * 36 * 4>>>(pA, pB, WQ_B3DW, b3_dw_b,
                                               32, 56, 56, scales, 7, 8, 5);
    pw_kernel<128, 256><<<dim3(25, 8), 256>>>(pB, pA, WP_B3PW, b3_pw_b,
                                              3136, scales, 8, 9, 6);
    pool_kernel<<<784, 256>>>(pA, pB, 64, 56, 56, scales, 9, 10);

    // head
    gap_kernel<<<512, 128>>>(pB, scales);
    fc_kernel<<<1, 128>>>(fc_b, out);
}

// round 7
// speedup vs baseline: 3.6261x; 1.0692x over previous
#include <cuda_runtime.h>
#include <cuda_bf16.h>

// ---------------------------------------------------------------------------
// Scratch (allocation-free: __device__ globals)
// Activations live as packed int8 in N[C/4]HW[4c] layout (one u32 = 4 channels
// of one pixel). u8 after ReLU-fq stages, s8 after pool-fq stages.
// ---------------------------------------------------------------------------
__device__ unsigned g_bufA[8 * 1024 * 1024];   // 32 MB ping (u32 words)
__device__ unsigned g_bufB[8 * 1024 * 1024];   // 32 MB pong
__device__ signed char g_wqi[52000];           // quantized int8 weights arena
__device__ unsigned g_wpk[14336];              // packed weights (u32)
__device__ float g_wscale[8];                  // per-tensor weight scales
__device__ float g_gap[2048];                  // [8,256] pooled features (float)

// byte-arena offsets (same order as wq srcs)
#define WQ_CONV1 0
#define WQ_B1DW  1728
#define WQ_B1PW  2304
#define WQ_B2DW  6400
#define WQ_B2PW  6976
#define WQ_B3DW  15168
#define WQ_B3PW  16320
#define WQ_FC    49088
// packed offsets (u32 units)
#define WP_B1PW  0
#define WP_B2PW  1024
#define WP_B3PW  3072
#define WP_C1    11264
#define WP_B1DW  11840
#define WP_B2DW  12224
#define WP_B3DW  12608

__device__ __forceinline__ float fqv(float x, float s, float lo, float hi) {
    float q = rintf(x / s);
    q = fminf(fmaxf(q, lo), hi);
    return q * s;
}

__device__ __forceinline__ void dp4a_us(int& acc, unsigned a, unsigned b) {
    asm("dp4a.u32.s32 %0, %1, %2, %3;" : "=r"(acc) : "r"(a), "r"(b), "r"(acc));
}
__device__ __forceinline__ void dp4a_ss(int& acc, unsigned a, unsigned b) {
    asm("dp4a.s32.s32 %0, %1, %2, %3;" : "=r"(acc) : "r"(a), "r"(b), "r"(acc));
}

__device__ __forceinline__ int clampi(int v, int lo, int hi) {
    return min(max(v, lo), hi);
}

// ---------------------------------------------------------------------------
// Weight quantize: int8 arena + packed pw/conv1/dw u32 + scales. 1 block/tensor.
// ---------------------------------------------------------------------------
__global__ void wq_kernel(const float* w0, const float* w1, const float* w2,
                          const float* w3, const float* w4, const float* w5,
                          const float* w6, const float* w7) {
    __shared__ float red[256];
    __shared__ signed char sq[32768];
    const float* srcs[8] = {w0, w1, w2, w3, w4, w5, w6, w7};
    const int sizes[8] = {1728, 576, 4096, 576, 8192, 1152, 32768, 2560};
    const int offs[8]  = {WQ_CONV1, WQ_B1DW, WQ_B1PW, WQ_B2DW,
                          WQ_B2PW, WQ_B3DW, WQ_B3PW, WQ_FC};
    const int cins[8]  = {0, 0, 64, 0, 64, 0, 128, 0};
    const int pwo[8]   = {-1, -1, WP_B1PW, -1, WP_B2PW, -1, WP_B3PW, -1};
    const int dwo[8]   = {-1, WP_B1DW, -1, WP_B2DW, -1, WP_B3DW, -1, -1};
    int t = blockIdx.x;
    const float* w = srcs[t];
    int n = sizes[t];

    float m = 0.0f;
    for (int i = threadIdx.x; i < n; i += 256) m = fmaxf(m, fabsf(w[i]));
    red[threadIdx.x] = m;
    __syncthreads();
    for (int s = 128; s > 0; s >>= 1) {
        if (threadIdx.x < s)
            red[threadIdx.x] = fmaxf(red[threadIdx.x], red[threadIdx.x + s]);
        __syncthreads();
    }
    float scale = red[0] / 127.0f;
    for (int i = threadIdx.x; i < n; i += 256) {
        int q = clampi(__float2int_rn(w[i] / scale), -127, 127);
        sq[i] = (signed char)q;
        g_wqi[offs[t] + i] = (signed char)q;
    }
    if (threadIdx.x == 0) g_wscale[t] = scale;
    __syncthreads();

    if (pwo[t] >= 0) {
        int CIN = cins[t], COUT = n / CIN;
        int npk = n / 4;
        for (int i = threadIdx.x; i < npk; i += 256) {
            int ic4 = i / COUT, oc = i % COUT;
            unsigned b0 = (unsigned char)sq[oc * CIN + ic4 * 4 + 0];
            unsigned b1 = (unsigned char)sq[oc * CIN + ic4 * 4 + 1];
            unsigned b2 = (unsigned char)sq[oc * CIN + ic4 * 4 + 2];
            unsigned b3 = (unsigned char)sq[oc * CIN + ic4 * 4 + 3];
            g_wpk[pwo[t] + i] = b0 | (b1 << 8) | (b2 << 16) | (b3 << 24);
        }
    }
    if (dwo[t] >= 0) {
        // dw pack: per channel c, per ky: wA=[w0,w1,w2,0], wB=[0,w0,w1,w2]
        int C = n / 9;
        for (int i = threadIdx.x; i < C * 3; i += 256) {
            int c = i / 3, ky = i % 3;
            unsigned b0 = (unsigned char)sq[c * 9 + ky * 3 + 0];
            unsigned b1 = (unsigned char)sq[c * 9 + ky * 3 + 1];
            unsigned b2 = (unsigned char)sq[c * 9 + ky * 3 + 2];
            g_wpk[dwo[t] + i * 2 + 0] = b0 | (b1 << 8) | (b2 << 16);
            g_wpk[dwo[t] + i * 2 + 1] = (b0 << 8) | (b1 << 16) | (b2 << 24);
        }
    }
    if (t == 0) {
        // conv1 pack: [oc][9 taps], bytes = [ic0, ic1, ic2, 0]
        for (int i = threadIdx.x; i < 576; i += 256) {
            int oc = i / 9, k = i % 9;
            unsigned b0 = (unsigned char)sq[oc * 27 + 0 + k];
            unsigned b1 = (unsigned char)sq[oc * 27 + 9 + k];
            unsigned b2 = (unsigned char)sq[oc * 27 + 18 + k];
            g_wpk[WP_C1 + i] = b0 | (b1 << 8) | (b2 << 16);
        }
    }
}

// ---------------------------------------------------------------------------
// Input quantize + pack: fq(x,s0,s8) -> [n][224*224] u32 of [c0,c1,c2,0].
// ---------------------------------------------------------------------------
__global__ void quant_input_kernel(const float* __restrict__ x,
                                   unsigned* __restrict__ out,
                                   const float* __restrict__ scales) {
    int idx = blockIdx.x * 256 + threadIdx.x;       // 100352 total
    int n = idx / 12544;
    int p4 = (idx % 12544) * 4;
    float inv_s0 = 1.0f / scales[0];
    const float* base = x + (size_t)n * 3 * 50176 + p4;
    float4 c0 = *(const float4*)(base);
    float4 c1 = *(const float4*)(base + 50176);
    float4 c2 = *(const float4*)(base + 100352);
    const float* f0 = &c0.x;
    const float* f1 = &c1.x;
    const float* f2 = &c2.x;
    uint4 pk;
    unsigned* pw = &pk.x;
    #pragma unroll
    for (int j = 0; j < 4; j++) {
        unsigned b0 = (unsigned)(clampi(__float2int_rn(f0[j] * inv_s0), -128, 127) & 0xFF);
        unsigned b1 = (unsigned)(clampi(__float2int_rn(f1[j] * inv_s0), -128, 127) & 0xFF);
        unsigned b2 = (unsigned)(clampi(__float2int_rn(f2[j] * inv_s0), -128, 127) & 0xFF);
        pw[j] = b0 | (b1 << 8) | (b2 << 16);
    }
    *(uint4*)&out[(size_t)n * 50176 + p4] = pk;
}

// ---------------------------------------------------------------------------
// conv1 (int): packed s8 input -> 3x3 conv (3->64, pad 1) via dp4a
// + bias + relu + fq(s1, u8 bytes). Block (8,32): 32x32 tile, 4 px/thread.
// ---------------------------------------------------------------------------
__global__ void conv1_kernel(const unsigned* __restrict__ xin,
                             const float* __restrict__ bias,
                             const float* __restrict__ scales,
                             unsigned* __restrict__ out) {
    __shared__ unsigned s_pix[34 * 34];
    __shared__ unsigned s_w[576];
    __shared__ float s_b[64];
    int n = blockIdx.z;
    int x0 = blockIdx.x * 32, y0 = blockIdx.y * 32;
    int tid = threadIdx.y * 8 + threadIdx.x;

    for (int i = tid; i < 576; i += 256) s_w[i] = g_wpk[WP_C1 + i];
    if (tid < 64) s_b[tid] = bias[tid];

    const unsigned* xp = xin + (size_t)n * 50176;
    for (int i = tid; i < 34 * 34; i += 256) {
        int ly = i / 34, lx = i % 34;
        int gy = y0 + ly - 1, gx = x0 + lx - 1;
        unsigned v = 0;
        if (gy >= 0 && gy < 224 && gx >= 0 && gx < 224)
            v = xp[gy * 224 + gx];
        s_pix[i] = v;
    }
    __syncthreads();

    int tx = threadIdx.x, ty = threadIdx.y;
    int x4 = tx * 4;

    unsigned p[3][6];
    #pragma unroll
    for (int ky = 0; ky < 3; ky++)
        #pragma unroll
        for (int dx = 0; dx < 6; dx++)
            p[ky][dx] = s_pix[(ty + ky) * 34 + x4 + dx];

    float inv_s1 = 1.0f / scales[1];
    float A = scales[0] * g_wscale[0] * inv_s1;
    size_t obase = ((size_t)(n * 16) * 224 + (y0 + ty)) * 224 + x0 + x4;

    for (int ocg = 0; ocg < 16; ocg++) {
        int acc[4][4] = {};   // [oc-in-group][px]
        #pragma unroll
        for (int j = 0; j < 4; j++) {
            const unsigned* wp = &s_w[(ocg * 4 + j) * 9];
            #pragma unroll
            for (int ky = 0; ky < 3; ky++)
                #pragma unroll
                for (int kx = 0; kx < 3; kx++) {
                    unsigned w = wp[ky * 3 + kx];
                    dp4a_ss(acc[j][0], p[ky][kx + 0], w);
                    dp4a_ss(acc[j][1], p[ky][kx + 1], w);
                    dp4a_ss(acc[j][2], p[ky][kx + 2], w);
                    dp4a_ss(acc[j][3], p[ky][kx + 3], w);
                }
        }
        uint4 pk;
        unsigned* pw = &pk.x;
        #pragma unroll
        for (int pt = 0; pt < 4; pt++) {
            unsigned v = 0;
            #pragma unroll
            for (int j = 0; j < 4; j++) {
                float B = s_b[ocg * 4 + j] * inv_s1;
                int q = clampi(__float2int_rn(fmaf(A, (float)acc[j][pt], B)), 0, 255);
                v |= (unsigned)q << (8 * j);
            }
            pw[pt] = v;
        }
        *(uint4*)&out[obase + (size_t)ocg * 50176] = pk;
    }
}

// ---------------------------------------------------------------------------
// Depthwise 3x3 (pad 1) + bias + relu + fq(u8) via byte_perm + dp4a.
// Thread: 4 px x 4 channels. Per (row, ch): 5 PRMT + 4 dp4a.
// ---------------------------------------------------------------------------
template <bool SIGNED>
__global__ void dw_kernel(const unsigned* __restrict__ in,
                          unsigned* __restrict__ out,
                          int wpko, const float* __restrict__ bias,
                          int G, int H, int W,
                          const float* __restrict__ scales,
                          int si_in, int si_out, int wsi) {
    extern __shared__ unsigned s_dw[];  // [G*4 ch][3 ky][2] packed weight words
    int tid = threadIdx.x;
    for (int i = tid; i < G * 24; i += 256) s_dw[i] = g_wpk[wpko + i];
    __syncthreads();

    int idx = blockIdx.x * 256 + tid;
    int W4 = W >> 2;
    int x4 = (idx % W4) * 4;
    int t = idx / W4;
    int yy = t % H; t /= H;
    int g = t % G;
    int n = t / G;

    // preload packed weights for this channel group
    unsigned wA[4][3], wB[4][3];
    #pragma unroll
    for (int j = 0; j < 4; j++)
        #pragma unroll
        for (int ky = 0; ky < 3; ky++) {
            wA[j][ky] = s_dw[((g * 4 + j) * 3 + ky) * 2 + 0];
            wB[j][ky] = s_dw[((g * 4 + j) * 3 + ky) * 2 + 1];
        }

    const unsigned* p = in + (size_t)(n * G + g) * H * W;
    int acc[4][4] = {};   // [ch][px]

    #pragma unroll
    for (int ky = 0; ky < 3; ky++) {
        int gy = yy + ky - 1;
        if (gy < 0 || gy >= H) continue;
        const unsigned* rp = p + (size_t)gy * W;
        uint4 mm = *(const uint4*)&rp[x4];
        unsigned v0 = (x4 > 0) ? rp[x4 - 1] : 0u;
        unsigned v5 = (x4 + 4 < W) ? rp[x4 + 4] : 0u;
        #pragma unroll
        for (int j = 0; j < 4; j++) {
            unsigned sel = (unsigned)j | ((unsigned)(j + 4) << 4);
            unsigned t01 = __byte_perm(v0, mm.x, sel);      // [bj(v0), bj(v1)]
            unsigned t23 = __byte_perm(mm.y, mm.z, sel);    // [bj(v2), bj(v3)]
            unsigned t45 = __byte_perm(mm.w, v5, sel);      // [bj(v4), bj(v5)]
            unsigned s0 = __byte_perm(t01, t23, 0x5410);    // [x-1,x0,x1,x2]
            unsigned s1 = __byte_perm(t23, t45, 0x5410);    // [x1,x2,x3,x4]
            if (SIGNED) {
                dp4a_ss(acc[j][0], s0, wA[j][ky]);
                dp4a_ss(acc[j][1], s0, wB[j][ky]);
                dp4a_ss(acc[j][2], s1, wA[j][ky]);
                dp4a_ss(acc[j][3], s1, wB[j][ky]);
            } else {
                dp4a_us(acc[j][0], s0, wA[j][ky]);
                dp4a_us(acc[j][1], s0, wB[j][ky]);
                dp4a_us(acc[j][2], s1, wA[j][ky]);
                dp4a_us(acc[j][3], s1, wB[j][ky]);
            }
        }
    }

    float inv_o = 1.0f / scales[si_out];
    float A = scales[si_in] * g_wscale[wsi] * inv_o;
    float B[4];
    #pragma unroll
    for (int j = 0; j < 4; j++) B[j] = bias[g * 4 + j] * inv_o;

    uint4 pk;
    unsigned* pw = &pk.x;
    #pragma unroll
    for (int pp = 0; pp < 4; pp++) {
        unsigned v = 0;
        #pragma unroll
        for (int j = 0; j < 4; j++) {
            int q = clampi(__float2int_rn(fmaf(A, (float)acc[j][pp], B[j])), 0, 255);
            v |= (unsigned)q << (8 * j);
        }
        pw[pp] = v;
    }
    *(uint4*)&out[(size_t)idx * 4] = pk;
}

// ---------------------------------------------------------------------------
// Pointwise 1x1 (CIN->COUT) via dp4a + bias + relu + fq(u8).
// Block tile: 128 px x 64 oc; thread 4 px x 8 oc.
// ---------------------------------------------------------------------------
template <int CIN, int COUT>
__global__ void __launch_bounds__(256)
pw_kernel(const unsigned* __restrict__ in, unsigned* __restrict__ out,
          int wpko, const float* __restrict__ bias,
          int HW, const float* __restrict__ scales,
          int si_in, int si_out, int wsi) {
    constexpr int CIN4 = CIN / 4;
    __shared__ unsigned s_x[CIN4 * 128];
    __shared__ unsigned s_w[CIN4 * 64];
    int tid = threadIdx.x;
    int n = blockIdx.y;
    int hw0 = blockIdx.x * 128;

    for (int e = tid * 4; e < CIN4 * 128; e += 1024) {
        int ic4 = e >> 7, pix = e & 127;
        *(uint4*)&s_x[e] =
            *(const uint4*)&in[(size_t)(n * CIN4 + ic4) * HW + hw0 + pix];
    }

    float inv_o = 1.0f / scales[si_out];
    float A = scales[si_in] * g_wscale[wsi] * inv_o;
    int pxA = (tid & 31) * 4;
    int ocl = (tid >> 5) * 8;
    bool ok = (hw0 + pxA) < HW;

    for (int oc0 = 0; oc0 < COUT; oc0 += 64) {
        __syncthreads();
        for (int e = tid; e < CIN4 * 64; e += 256) {
            int ic4 = e >> 6, o = e & 63;
            s_w[e] = g_wpk[wpko + ic4 * COUT + oc0 + o];
        }
        __syncthreads();

        int acc[8][4] = {};
        #pragma unroll 4
        for (int ic4 = 0; ic4 < CIN4; ic4++) {
            uint4 xa = *(const uint4*)&s_x[ic4 * 128 + pxA];
            uint4 wAv = *(const uint4*)&s_w[ic4 * 64 + ocl];
            uint4 wBv = *(const uint4*)&s_w[ic4 * 64 + ocl + 4];
            unsigned ws8[8] = {wAv.x, wAv.y, wAv.z, wAv.w, wBv.x, wBv.y, wBv.z, wBv.w};
            #pragma unroll
            for (int o = 0; o < 8; o++) {
                dp4a_us(acc[o][0], xa.x, ws8[o]);
                dp4a_us(acc[o][1], xa.y, ws8[o]);
                dp4a_us(acc[o][2], xa.z, ws8[o]);
                dp4a_us(acc[o][3], xa.w, ws8[o]);
            }
        }

        if (ok) {
            #pragma unroll
            for (int og = 0; og < 2; og++) {
                float B[4];
                #pragma unroll
                for (int j = 0; j < 4; j++)
                    B[j] = bias[oc0 + ocl + og * 4 + j] * inv_o;
                int oc4 = (oc0 + ocl) / 4 + og;
                size_t obase = (size_t)(n * (COUT / 4) + oc4) * HW + hw0;
                uint4 pk;
                unsigned* pw = &pk.x;
                #pragma unroll
                for (int pt = 0; pt < 4; pt++) {
                    unsigned v = 0;
                    #pragma unroll
                    for (int j = 0; j < 4; j++) {
                        int q = clampi(__float2int_rn(
                            fmaf(A, (float)acc[og * 4 + j][pt], B[j])), 0, 255);
                        v |= (unsigned)q << (8 * j);
                    }
                    pw[pt] = v;
                }
                *(uint4*)&out[obase + pxA] = pk;
            }
        }
    }
}

// ---------------------------------------------------------------------------
// 2x2 maxpool stride 2 (per-byte vmax on u8) + requant to s8.
// ---------------------------------------------------------------------------
__global__ void pool_kernel(const unsigned* __restrict__ in,
                            unsigned* __restrict__ out,
                            int G, int H, int W,
                            const float* __restrict__ scales,
                            int si_in, int si_out) {
    int OH = H >> 1, OW = W >> 1, OW2 = OW >> 1;
    int idx = blockIdx.x * 256 + threadIdx.x;
    int ox = (idx % OW2) * 2;
    int t = idx / OW2;
    int oy = t % OH; t /= OH;
    int g = t % G;
    int n = t / G;

    const unsigned* p = in + ((size_t)(n * G + g) * H + oy * 2) * W + ox * 2;
    uint4 a = *(const uint4*)p;
    uint4 b = *(const uint4*)(p + W);
    unsigned m0 = __vmaxu4(__vmaxu4(a.x, a.y), __vmaxu4(b.x, b.y));
    unsigned m1 = __vmaxu4(__vmaxu4(a.z, a.w), __vmaxu4(b.z, b.w));

    float r = scales[si_in] / scales[si_out];
    uint2 pk;
    unsigned mm[2] = {m0, m1};
    unsigned* pw = &pk.x;
    #pragma unroll
    for (int p2 = 0; p2 < 2; p2++) {
        unsigned v = 0;
        #pragma unroll
        for (int j = 0; j < 4; j++) {
            int byte = (int)((mm[p2] >> (8 * j)) & 0xFF);
            int q = clampi(__float2int_rn((float)byte * r), -128, 127);
            v |= (unsigned)(q & 0xFF) << (8 * j);
        }
        pw[p2] = v;
    }
    out[((size_t)(n * G + g) * OH + oy) * OW + ox] = pk.x;
    out[((size_t)(n * G + g) * OH + oy) * OW + ox + 1] = pk.y;
}

// ---------------------------------------------------------------------------
// Global avg pool 28x28 (s8 input) + fq(s[11], int8) -> g_gap floats.
// ---------------------------------------------------------------------------
__global__ void gap_kernel(const unsigned* __restrict__ in,
                           const float* __restrict__ scales) {
    __shared__ int4 red[128];
    int bc = blockIdx.x;        // n*64 + g
    const unsigned* p = in + (size_t)bc * 784;
    int s0 = 0, s1 = 0, s2 = 0, s3 = 0;
    for (int i = threadIdx.x; i < 784; i += 128) {
        unsigned v = p[i];
        s0 += (int)(v << 24) >> 24;
        s1 += (int)(v << 16) >> 24;
        s2 += (int)(v << 8) >> 24;
        s3 += (int)v >> 24;
    }
    red[threadIdx.x] = make_int4(s0, s1, s2, s3);
    __syncthreads();
    for (int s = 64; s > 0; s >>= 1) {
        if (threadIdx.x < s) {
            int4 a = red[threadIdx.x], b = red[threadIdx.x + s];
            red[threadIdx.x] = make_int4(a.x + b.x, a.y + b.y, a.z + b.z, a.w + b.w);
        }
        __syncthreads();
    }
    if (threadIdx.x == 0) {
        float s10 = scales[10], s11 = scales[11];
        int4 r = red[0];
        int n = bc >> 6, g = bc & 63;
        int sums[4] = {r.x, r.y, r.z, r.w};
        #pragma unroll
        for (int j = 0; j < 4; j++) {
            float m = s10 * (float)sums[j] / 784.0f;
            g_gap[n * 256 + g * 4 + j] = fqv(m, s11, -128.0f, 127.0f);
        }
    }
}

// ---------------------------------------------------------------------------
// FC: [8,256] @ Wq^T + b -> [8,10]
// ---------------------------------------------------------------------------
__global__ void fc_kernel(const float* __restrict__ fc_b, float* __restrict__ out) {
    int t = threadIdx.x;
    if (t < 80) {
        int n = t / 10, k = t % 10;
        float ws = g_wscale[7];
        float acc = fc_b[k];
        const signed char* w = g_wqi + WQ_FC + k * 256;
        const float* g = g_gap + n * 256;
        #pragma unroll 8
        for (int i = 0; i < 256; i++) acc += (float)w[i] * ws * g[i];
        out[t] = acc;
    }
}

// ---------------------------------------------------------------------------
// Launch
// ---------------------------------------------------------------------------
extern "C" void kernel_launch(void* const* d_in, const int* in_sizes, int n_in,
                              void* d_out, int out_size) {
    const float* x       = (const float*)d_in[0];
    const float* scales  = (const float*)d_in[1];
    const float* conv1_w = (const float*)d_in[2];
    const float* conv1_b = (const float*)d_in[3];
    const float* b1_dw_w = (const float*)d_in[4];
    const float* b1_dw_b = (const float*)d_in[5];
    const float* b1_pw_w = (const float*)d_in[6];
    const float* b1_pw_b = (const float*)d_in[7];
    const float* b2_dw_w = (const float*)d_in[8];
    const float* b2_dw_b = (const float*)d_in[9];
    const float* b2_pw_w = (const float*)d_in[10];
    const float* b2_pw_b = (const float*)d_in[11];
    const float* b3_dw_w = (const float*)d_in[12];
    const float* b3_dw_b = (const float*)d_in[13];
    const float* b3_pw_w = (const float*)d_in[14];
    const float* b3_pw_b = (const float*)d_in[15];
    const float* fc_b    = (const float*)d_in[17];
    float* out = (float*)d_out;

    unsigned *pA = nullptr, *pB = nullptr;
    cudaGetSymbolAddress((void**)&pA, g_bufA);
    cudaGetSymbolAddress((void**)&pB, g_bufB);

    // 1) quantize weights (int8 arena + packed + scales)
    wq_kernel<<<8, 256>>>(conv1_w, b1_dw_w, b1_pw_w, b2_dw_w,
                          b2_pw_w, b3_dw_w, b3_pw_w, (const float*)d_in[16]);

    // 2) quantize + pack input -> B;  conv1 (int) -> A (u8, N[16]HW[4])
    quant_input_kernel<<<392, 256>>>(x, pB, scales);
    {
        dim3 cb(8, 32), cg(7, 7, 8);
        conv1_kernel<<<cg, cb>>>(pB, conv1_b, scales, pA);
    }

    // block 1 @ 224x224, C=64 (G=16)
    dw_kernel<false><<<6272, 256, 16 * 24 * 4>>>(pA, pB, WP_B1DW, b1_dw_b,
                                                 16, 224, 224, scales, 1, 2, 1);
    pw_kernel<64, 64><<<dim3(392, 8), 256>>>(pB, pA, WP_B1PW, b1_pw_b,
                                             50176, scales, 2, 3, 2);
    pool_kernel<<<3136, 256>>>(pA, pB, 16, 224, 224, scales, 3, 4);

    // block 2 @ 112x112, 64 -> 128
    dw_kernel<true><<<1568, 256, 16 * 24 * 4>>>(pB, pA, WP_B2DW, b2_dw_b,
                                                16, 112, 112, scales, 4, 5, 3);
    pw_kernel<64, 128><<<dim3(98, 8), 256>>>(pA, pB, WP_B2PW, b2_pw_b,
                                             12544, scales, 5, 6, 4);
    pool_kernel<<<1568, 256>>>(pB, pA, 32, 112, 112, scales, 6, 7);

    // block 3 @ 56x56, 128 -> 256
    dw_kernel<true><<<784, 256, 32 * 24 * 4>>>(pA, pB, WP_B3DW, b3_dw_b,
                                               32, 56, 56, scales, 7, 8, 5);
    pw_kernel<128, 256><<<dim3(25, 8), 256>>>(pB, pA, WP_B3PW, b3_pw_b,
                                              3136, scales, 8, 9, 6);
    pool_kernel<<<784, 256>>>(pA, pB, 64, 56, 56, scales, 9, 10);

    // head
    gap_kernel<<<512, 128>>>(pB, scales);
    fc_kernel<<<1, 128>>>(fc_b, out);
}